// round 13
// baseline (speedup 1.0000x reference)
#include <cuda_runtime.h>
#include <cuda_fp16.h>
#include <math.h>
#include <stdint.h>

#define B_  4
#define S_  2048
#define SV_ 50
#define E_  1024
#define VP_ 128   // padded v rows per batch

typedef __half fp16;

// ---------------- scratch (device globals) ----------------------------------
__device__ float g_cs [B_*E_];
__device__ float g_cs2[B_*E_];

__device__ fp16 g_Qs[B_*S_*E_];
__device__ fp16 g_Ks[B_*S_*E_];
__device__ fp16 g_Wq16[E_*E_];
__device__ fp16 g_Wk16[E_*E_];
__device__ fp16 g_Wv16[E_*E_];
__device__ fp16 g_Wvq16[64*E_];
__device__ fp16 g_Wvk16[64*E_];
__device__ fp16 g_Vp[B_*VP_*E_];
__device__ fp16 g_vh[B_*VP_*E_];
__device__ fp16 g_qh[B_*S_*E_];
__device__ fp16 g_kh[B_*S_*E_];
__device__ fp16 g_vqh[B_*S_*VP_];
__device__ fp16 g_vkh[B_*S_*VP_];
__device__ fp16 g_fh[(size_t)B_*S_*S_];   // raw fp16 scores, then softmaxed fp16
__device__ fp16 g_q2b[B_*S_*E_];
__device__ fp16 g_k2b[B_*S_*E_];
__device__ fp16 g_q2h[B_*S_*E_];
__device__ fp16 g_k2h[B_*S_*E_];

// ---------------- PTX helpers ------------------------------------------------
__device__ __forceinline__ uint32_t smem_u32(const void* p) {
    uint32_t a;
    asm("{ .reg .u64 t; cvta.to.shared.u64 t, %1; cvt.u32.u64 %0, t; }"
        : "=r"(a) : "l"(p));
    return a;
}
__device__ __forceinline__ void cp_async16(uint32_t dst, const void* src) {
    asm volatile("cp.async.cg.shared.global [%0], [%1], 16;"
                 :: "r"(dst), "l"(src) : "memory");
}
#define CP_COMMIT() asm volatile("cp.async.commit_group;" ::: "memory")
#define CP_WAIT(n)  asm volatile("cp.async.wait_group %0;" :: "n"(n) : "memory")

#define LDMATRIX_X4(r0, r1, r2, r3, addr) \
    asm volatile("ldmatrix.sync.aligned.m8n8.x4.shared.b16 {%0,%1,%2,%3}, [%4];" \
        : "=r"(r0), "=r"(r1), "=r"(r2), "=r"(r3) : "r"(addr))

#define LDMATRIX_X4_T(r0, r1, r2, r3, addr) \
    asm volatile("ldmatrix.sync.aligned.m8n8.x4.trans.shared.b16 {%0,%1,%2,%3}, [%4];" \
        : "=r"(r0), "=r"(r1), "=r"(r2), "=r"(r3) : "r"(addr))

#define MMA_F16(d, a, b) \
    asm volatile("mma.sync.aligned.m16n8k16.row.col.f32.f16.f16.f32 " \
        "{%0,%1,%2,%3},{%4,%5,%6,%7},{%8,%9},{%0,%1,%2,%3};" \
        : "+f"((d)[0]), "+f"((d)[1]), "+f"((d)[2]), "+f"((d)[3]) \
        : "r"((a)[0]), "r"((a)[1]), "r"((a)[2]), "r"((a)[3]), \
          "r"((b)[0]), "r"((b)[1]))

// ---------------- fp16 HMMA GEMM (NT/NN, paired, fp16 beta-base) -------------
// BK=64, 3-stage cp.async ring (2 CTAs/SM).
// NT=true : C = alpha * A[M,K] @ B[N,K]^T   (B row-major [N,K])
// NT=false: C = alpha * A[M,K] @ B[K,N]     (B row-major [K,N], ldmatrix.trans)
// BM16: epilogue adds beta * P (fp16). PAIR: blockIdx.z = 2*batch + sel.
constexpr int HM_BM = 128, HM_BN = 128, HM_BK = 64;
constexpr int HM_LDSA = HM_BK + 8;              // 72 elems (A / NT-B row stride)
constexpr int HM_TILEA_B = HM_BM * HM_LDSA * 2; // 18432 bytes
constexpr int HM_LDSB = HM_BN + 8;              // 136 elems (NN-B row stride)
constexpr int HM_STAGE_B = 2 * HM_TILEA_B;      // 36864 bytes (A | B)
constexpr int HM_SMEM_BYTES = 3 * HM_STAGE_B;   // 110592

template<bool NT, bool BM16, bool PAIR>
__global__ void __launch_bounds__(256, 2)
hmma_g(const fp16* __restrict__ A0, const fp16* __restrict__ A1,
       const fp16* __restrict__ B0, const fp16* __restrict__ B1,
       float* __restrict__ C0, float* __restrict__ C1,
       fp16* __restrict__ O0, fp16* __restrict__ O1,
       const fp16* __restrict__ P0, const fp16* __restrict__ P1,
       const float* __restrict__ bias0, const float* __restrict__ bias1,
       int M, int N, int K, int lda, int ldb, int ldc,
       long long sA, long long sB, long long sC, long long sBias,
       float alpha0, float alpha1, float beta)
{
    extern __shared__ fp16 sm[];
    const uint32_t sbase = smem_u32(sm);

    int sel, zb;
    if (PAIR) { sel = blockIdx.z & 1; zb = blockIdx.z >> 1; }
    else      { sel = 0;              zb = blockIdx.z; }

    const fp16* Ah = (PAIR && sel ? A1 : A0) + (long long)zb * sA;
    const fp16* Bh = (PAIR && sel ? B1 : B0) + (long long)zb * sB;
    float* C  = (PAIR && sel) ? C1 : C0;
    fp16*  Oh = (PAIR && sel) ? O1 : O0;
    const fp16* P = BM16 ? ((PAIR && sel) ? P1 : P0) : nullptr;
    const float* bias = (PAIR && sel) ? bias1 : bias0;
    const float alpha = (PAIR && sel) ? alpha1 : alpha0;
    const long long co = (long long)zb * sC;
    const float* bp = bias ? (bias + (long long)zb * sBias) : nullptr;

    const int tid = threadIdx.x;
    const int warp = tid >> 5, lane = tid & 31;
    const int wm = warp & 3, wn = warp >> 2;         // 4x2 warps: 32m x 64n
    const int bm = blockIdx.y * HM_BM;
    const int bn = blockIdx.x * HM_BN;
    const int NT_ = K / HM_BK;

    auto issue = [&](int it) {
        const uint32_t sb0 = sbase + (uint32_t)(it % 3) * HM_STAGE_B;
        const long long ko = (long long)it * HM_BK;
        if (it < NT_) {
#pragma unroll
            for (int j = 0; j < 4; j++) {            // A: 1024 chunks (16B)
                int c = tid * 4 + j;
                int r = c >> 3, e = (c & 7) * 8;
                cp_async16(sb0 + (uint32_t)(r * HM_LDSA + e) * 2,
                           Ah + (long long)(bm + r) * lda + ko + e);
            }
            if (NT) {
#pragma unroll
                for (int j = 0; j < 4; j++) {
                    int c = tid * 4 + j;
                    int r = c >> 3, e = (c & 7) * 8;
                    cp_async16(sb0 + HM_TILEA_B + (uint32_t)(r * HM_LDSA + e) * 2,
                               Bh + (long long)(bn + r) * ldb + ko + e);
                }
            } else {
#pragma unroll
                for (int j = 0; j < 4; j++) {        // B: 64 rows x 128 cols
                    int c = tid * 4 + j;
                    int r = c >> 4, e = (c & 15) * 8;
                    cp_async16(sb0 + HM_TILEA_B + (uint32_t)(r * HM_LDSB + e) * 2,
                               Bh + (ko + r) * (long long)ldb + bn + e);
                }
            }
        }
        CP_COMMIT();   // uniform group count (empty groups complete immediately)
    };

    float acc[2][8][4];
#pragma unroll
    for (int m = 0; m < 2; m++)
#pragma unroll
        for (int n = 0; n < 8; n++)
#pragma unroll
            for (int j = 0; j < 4; j++) acc[m][n][j] = 0.f;

    issue(0);
    issue(1);

    const int lr  = lane & 15;
    const int lc8 = (lane >> 4) << 3;

    for (int kt = 0; kt < NT_; ++kt) {
        CP_WAIT(1);                      // all but newest group complete -> kt ready
        __syncthreads();
        issue(kt + 2);                   // refill of retired buffer, safe post-barrier
        const uint32_t sb0 = sbase + (uint32_t)(kt % 3) * HM_STAGE_B;
#pragma unroll
        for (int ks = 0; ks < 4; ks++) {
            const int k0 = ks * 16;
            uint32_t fA[2][4], fB[8][2];
#pragma unroll
            for (int t = 0; t < 2; t++) {
                uint32_t a = sb0 + (uint32_t)((wm*32 + t*16 + lr) * HM_LDSA + k0 + lc8) * 2;
                LDMATRIX_X4(fA[t][0], fA[t][1], fA[t][2], fA[t][3], a);
            }
            if (NT) {
#pragma unroll
                for (int p = 0; p < 4; p++) {
                    uint32_t a = sb0 + HM_TILEA_B
                               + (uint32_t)((wn*64 + p*16 + lr) * HM_LDSA + k0 + lc8) * 2;
                    uint32_t r0, r1, r2, r3;
                    LDMATRIX_X4(r0, r1, r2, r3, a);
                    fB[p*2][0]   = r0; fB[p*2][1]   = r2;
                    fB[p*2+1][0] = r1; fB[p*2+1][1] = r3;
                }
            } else {
#pragma unroll
                for (int p = 0; p < 4; p++) {
                    uint32_t a = sb0 + HM_TILEA_B
                               + (uint32_t)((k0 + lr) * HM_LDSB + wn*64 + p*16 + lc8) * 2;
                    uint32_t r0, r1, r2, r3;
                    LDMATRIX_X4_T(r0, r1, r2, r3, a);
                    fB[p*2][0]   = r0; fB[p*2][1]   = r1;
                    fB[p*2+1][0] = r2; fB[p*2+1][1] = r3;
                }
            }
#pragma unroll
            for (int m = 0; m < 2; m++)
#pragma unroll
                for (int n = 0; n < 8; n++) MMA_F16(acc[m][n], fA[m], fB[n]);
        }
    }

    // epilogue
    const int qr = lane >> 2, qc = (lane & 3) * 2;
#pragma unroll
    for (int mt = 0; mt < 2; mt++) {
#pragma unroll
        for (int nt = 0; nt < 8; nt++) {
            const int col = bn + wn*64 + nt*8 + qc;
#pragma unroll
            for (int h = 0; h < 2; h++) {
                const int row = bm + wm*32 + mt*16 + qr + h*8;
                const long long o = co + (long long)row * ldc + col;
                float2 v;
                v.x = alpha * acc[mt][nt][h*2 + 0];
                v.y = alpha * acc[mt][nt][h*2 + 1];
                if (BM16) {
                    __half2 pb = *(const __half2*)(P + o);
                    v.x += beta * __half2float(__low2half(pb));
                    v.y += beta * __half2float(__high2half(pb));
                }
                if (bp) { v.x += bp[col]; v.y += bp[col + 1]; }
                if (C)  *(float2*)(C + o) = v;
                if (Oh) *(__half2*)(Oh + o) =
                        __halves2half2(__float2half_rn(v.x), __float2half_rn(v.y));
            }
        }
    }
}

// ---------------- convert kernels --------------------------------------------
template<bool TANH>
__global__ void cvt2_k(const float* __restrict__ x0, const float* __restrict__ x1,
                       fp16* __restrict__ h0, fp16* __restrict__ h1, long long n)
{
    const float* x = blockIdx.y ? x1 : x0;
    fp16* h = blockIdx.y ? h1 : h0;
    long long i = ((long long)blockIdx.x * blockDim.x + threadIdx.x) * 4;
    if (i >= n) return;
    float4 v = *(const float4*)(x + i);
    if (TANH) { v.x = tanhf(v.x); v.y = tanhf(v.y); v.z = tanhf(v.z); v.w = tanhf(v.w); }
    __half2* hp = (__half2*)(h + i);
    hp[0] = __halves2half2(__float2half_rn(v.x), __float2half_rn(v.y));
    hp[1] = __halves2half2(__float2half_rn(v.z), __float2half_rn(v.w));
}

__global__ void cvt3_k(const float* __restrict__ x0, const float* __restrict__ x1,
                       const float* __restrict__ x2,
                       fp16* __restrict__ h0, fp16* __restrict__ h1,
                       fp16* __restrict__ h2, long long n)
{
    const float* x = (blockIdx.y == 0) ? x0 : (blockIdx.y == 1) ? x1 : x2;
    fp16* h = (blockIdx.y == 0) ? h0 : (blockIdx.y == 1) ? h1 : h2;
    long long i = ((long long)blockIdx.x * blockDim.x + threadIdx.x) * 4;
    if (i >= n) return;
    float4 v = *(const float4*)(x + i);
    __half2* hp = (__half2*)(h + i);
    hp[0] = __halves2half2(__float2half_rn(v.x), __float2half_rn(v.y));
    hp[1] = __halves2half2(__float2half_rn(v.z), __float2half_rn(v.w));
}

__global__ void padcvtW2_k(const float* __restrict__ W0, const float* __restrict__ W1,
                           fp16* __restrict__ h0, fp16* __restrict__ h1)
{
    const float* W = blockIdx.y ? W1 : W0;
    fp16* h = blockIdx.y ? h1 : h0;
    long long i = ((long long)blockIdx.x * blockDim.x + threadIdx.x) * 4;
    if (i >= 64 * E_) return;
    int r = (int)(i / E_), e = (int)(i % E_);
    float4 v = make_float4(0.f, 0.f, 0.f, 0.f);
    if (r < SV_) v = *(const float4*)(W + (long long)r * E_ + e);
    __half2* hp = (__half2*)(h + i);
    hp[0] = __halves2half2(__float2half_rn(v.x), __float2half_rn(v.y));
    hp[1] = __halves2half2(__float2half_rn(v.z), __float2half_rn(v.w));
}

__global__ void padcvtV_k(const float* __restrict__ V, fp16* __restrict__ h)
{
    long long i = ((long long)blockIdx.x * blockDim.x + threadIdx.x) * 4;
    if (i >= (long long)B_ * VP_ * E_) return;
    int b = (int)(i / (VP_ * E_));
    int rem = (int)(i % (VP_ * E_));
    int r = rem / E_, e = rem % E_;
    float4 v = make_float4(0.f, 0.f, 0.f, 0.f);
    if (r < SV_) {
        v = *(const float4*)(V + ((long long)(b * SV_ + r)) * E_ + e);
        v.x = tanhf(v.x); v.y = tanhf(v.y); v.z = tanhf(v.z); v.w = tanhf(v.w);
    }
    __half2* hp = (__half2*)(h + i);
    hp[0] = __halves2half2(__float2half_rn(v.x), __float2half_rn(v.y));
    hp[1] = __halves2half2(__float2half_rn(v.z), __float2half_rn(v.w));
}

// ---------------- softmax: fp16 scores in-place -> fp32 f + fp16 fh ----------
// cols must equal 8*256 = 2048
__global__ void softmax_cvt(fp16* __restrict__ h, float* __restrict__ x, int cols)
{
    long long r = blockIdx.x;
    fp16* hp = h + r * (long long)cols;
    float* p = x + r * (long long)cols;
    __shared__ float red[256];
    const int t = threadIdx.x;

    float vals[8];
#pragma unroll
    for (int i = 0; i < 8; i++) vals[i] = __half2float(hp[t + i * 256]);

    float mx = vals[0];
#pragma unroll
    for (int i = 1; i < 8; i++) mx = fmaxf(mx, vals[i]);
    red[t] = mx; __syncthreads();
    for (int s = 128; s > 0; s >>= 1) { if (t < s) red[t] = fmaxf(red[t], red[t + s]); __syncthreads(); }
    mx = red[0]; __syncthreads();

    float sum = 0.f;
#pragma unroll
    for (int i = 0; i < 8; i++) { vals[i] = expf(vals[i] - mx); sum += vals[i]; }
    red[t] = sum; __syncthreads();
    for (int s = 128; s > 0; s >>= 1) { if (t < s) red[t] += red[t + s]; __syncthreads(); }
    const float inv = 1.f / red[0];

#pragma unroll
    for (int i = 0; i < 8; i++) {
        float val = vals[i] * inv;
        p[t + i * 256] = val;
        hp[t + i * 256] = __float2half_rn(val);
    }
}

// colsum over fp16 input
__global__ void colsum16_k(const fp16* __restrict__ x, float* __restrict__ out,
                           int T, int E)
{
    int e = blockIdx.x * blockDim.x + threadIdx.x;
    int b = blockIdx.y;
    const fp16* p = x + (long long)b * T * E + e;
    float s = 0.f;
    for (int t = 0; t < T; t++) s += __half2float(p[(long long)t * E]);
    out[(long long)b * E + e] = s;
}

// ---------------- host launcher ----------------------------------------------
extern "C" void kernel_launch(void* const* d_in, const int* in_sizes, int n_in,
                              void* d_out, int out_size)
{
    const float* Q    = (const float*)d_in[0];
    const float* K    = (const float*)d_in[1];
    const float* V    = (const float*)d_in[2];
    const float* W_Q  = (const float*)d_in[3];
    const float* W_K  = (const float*)d_in[4];
    const float* W_v  = (const float*)d_in[5];
    const float* W_vq = (const float*)d_in[6];
    const float* W_vk = (const float*)d_in[7];

    float* out  = (float*)d_out;
    float* outQ = out;
    float* outK = out + (long long)B_ * S_ * E_;
    float* f    = out + 2ll * B_ * S_ * E_;

    float *cs, *cs2;
    cudaGetSymbolAddress((void**)&cs,  g_cs);
    cudaGetSymbolAddress((void**)&cs2, g_cs2);

    fp16 *Qs,*Ks,*Wq16,*Wk16,*Wv16,*Wvq16,*Wvk16,*Vp,*vh;
    fp16 *qh,*kh,*vqh,*vkh,*fh,*q2b,*k2b,*q2h,*k2h;
    cudaGetSymbolAddress((void**)&Qs,    g_Qs);
    cudaGetSymbolAddress((void**)&Ks,    g_Ks);
    cudaGetSymbolAddress((void**)&Wq16,  g_Wq16);
    cudaGetSymbolAddress((void**)&Wk16,  g_Wk16);
    cudaGetSymbolAddress((void**)&Wv16,  g_Wv16);
    cudaGetSymbolAddress((void**)&Wvq16, g_Wvq16);
    cudaGetSymbolAddress((void**)&Wvk16, g_Wvk16);
    cudaGetSymbolAddress((void**)&Vp,    g_Vp);
    cudaGetSymbolAddress((void**)&vh,    g_vh);
    cudaGetSymbolAddress((void**)&qh,    g_qh);
    cudaGetSymbolAddress((void**)&kh,    g_kh);
    cudaGetSymbolAddress((void**)&vqh,   g_vqh);
    cudaGetSymbolAddress((void**)&vkh,   g_vkh);
    cudaGetSymbolAddress((void**)&fh,    g_fh);
    cudaGetSymbolAddress((void**)&q2b,   g_q2b);
    cudaGetSymbolAddress((void**)&k2b,   g_k2b);
    cudaGetSymbolAddress((void**)&q2h,   g_q2h);
    cudaGetSymbolAddress((void**)&k2h,   g_k2h);

    cudaFuncSetAttribute(hmma_g<false,false,false>, cudaFuncAttributeMaxDynamicSharedMemorySize, HM_SMEM_BYTES);
    cudaFuncSetAttribute(hmma_g<false,false,true >, cudaFuncAttributeMaxDynamicSharedMemorySize, HM_SMEM_BYTES);
    cudaFuncSetAttribute(hmma_g<true ,false,false>, cudaFuncAttributeMaxDynamicSharedMemorySize, HM_SMEM_BYTES);
    cudaFuncSetAttribute(hmma_g<true ,false,true >, cudaFuncAttributeMaxDynamicSharedMemorySize, HM_SMEM_BYTES);
    cudaFuncSetAttribute(hmma_g<false,true ,true >, cudaFuncAttributeMaxDynamicSharedMemorySize, HM_SMEM_BYTES);

    const float inv = 1.0f / 32.0f;  // 1/sqrt(1024)
    const long long sQE = (long long)S_ * E_;
    const long long sSS = (long long)S_ * S_;
    const long long sVE = (long long)VP_ * E_;
    const long long sSV = (long long)S_ * VP_;
    const long long nQE = (long long)B_ * S_ * E_;

    // ---- stage 0: input conversions ----------------------------------------
    cvt2_k<true><<<dim3((int)(nQE/4/256), 2), 256>>>(Q, K, Qs, Ks, nQE);
    cvt3_k<<<dim3((int)((long long)E_*E_/4/256), 3), 256>>>(
        W_Q, W_K, W_v, Wq16, Wk16, Wv16, (long long)E_*E_);
    padcvtW2_k<<<dim3(64, 2), 256>>>(W_vq, W_vk, Wvq16, Wvk16);
    padcvtV_k<<<(int)((long long)B_*VP_*E_/4/256), 256>>>(V, Vp);

    // ---- stage 1: paired Q/K projections (NN, fp16 out only) + v -----------
    hmma_g<false,false,true><<<dim3(8,64,2), 256, HM_SMEM_BYTES>>>(
        Qs, Ks, Wq16, Wk16, nullptr, nullptr, qh, kh, nullptr, nullptr,
        nullptr, nullptr,
        B_*S_, E_, E_, E_, E_, E_, 0,0,0,0, 1.f, 1.f, 0.f);
    hmma_g<false,false,false><<<dim3(8,(B_*VP_)/128,1), 256, HM_SMEM_BYTES>>>(
        Vp, nullptr, Wv16, nullptr, nullptr, nullptr, vh, nullptr, nullptr, nullptr,
        nullptr, nullptr,
        B_*VP_, E_, E_, E_, E_, E_, 0,0,0,0, 1.f, 0.f, 0.f);

    colsum16_k<<<dim3(E_/256,B_), 256>>>(kh, cs, S_, E_);

    // ---- stage 3: raw fp16 scores -> softmax (writes fp32 f + fp16 fh) -----
    hmma_g<true,false,false><<<dim3(16,16,B_), 256, HM_SMEM_BYTES>>>(
        qh, nullptr, kh, nullptr, nullptr, nullptr, fh, nullptr, nullptr, nullptr,
        nullptr, nullptr,
        S_, S_, E_, E_, E_, S_, sQE, sQE, sSS, 0, inv, 0.f, 0.f);
    softmax_cvt<<<B_*S_, 256>>>(fh, f, S_);

    // ---- vq/vk paired (NT, N=VP=128) + q2/k2 base paired (NN) --------------
    hmma_g<true,false,true><<<dim3(VP_/128,16,2*B_), 256, HM_SMEM_BYTES>>>(
        qh, kh, vh, vh, nullptr, nullptr, vqh, vkh, nullptr, nullptr,
        nullptr, nullptr,
        S_, VP_, E_, E_, E_, VP_, sQE, sVE, sSV, 0, inv, inv, 0.f);
    hmma_g<false,false,true><<<dim3(8,16,2*B_), 256, HM_SMEM_BYTES>>>(
        vqh, vkh, Wvq16, Wvk16, nullptr, nullptr, q2b, k2b, nullptr, nullptr,
        nullptr, cs,
        S_, E_, 64, VP_, E_, E_, sSV, 0, sQE, E_, 1.f, 1.f, 0.f);

    // ---- stage 4: q2 = f@q + q2b ; k2 = -(f@k) + k2b (fp16 base + out) -----
    hmma_g<false,true,true><<<dim3(8,16,2*B_), 256, HM_SMEM_BYTES>>>(
        fh, fh, qh, kh, nullptr, nullptr, q2h, k2h, q2b, k2b,
        nullptr, nullptr,
        S_, E_, S_, S_, E_, E_, sSS, sQE, sQE, 0, 1.f, -1.f, 1.f);

    colsum16_k<<<dim3(E_/256,B_), 256>>>(k2h, cs2, S_, E_);

    // ---- stage 5: outputs (paired NN) --------------------------------------
    hmma_g<false,false,true><<<dim3(8,16,2*B_), 256, HM_SMEM_BYTES>>>(
        fh, fh, q2h, k2h, outQ, outK, nullptr, nullptr, nullptr, nullptr,
        nullptr, cs2,
        S_, E_, S_, S_, E_, E_, sSS, sQE, sQE, E_, 1.f, -1.f, 0.f);

    (void)in_sizes; (void)n_in; (void)out_size;
}

// round 14
// speedup vs baseline: 1.2098x; 1.2098x over previous
#include <cuda_runtime.h>
#include <cuda_fp16.h>
#include <math.h>
#include <stdint.h>

#define B_  4
#define S_  2048
#define SV_ 50
#define E_  1024
#define VP_ 128   // padded v rows per batch

typedef __half fp16;

// ---------------- scratch (device globals) ----------------------------------
__device__ float g_cs [B_*E_];
__device__ float g_cs2[B_*E_];

__device__ fp16 g_Qs[B_*S_*E_];
__device__ fp16 g_Ks[B_*S_*E_];
__device__ fp16 g_Wq16[E_*E_];
__device__ fp16 g_Wk16[E_*E_];
__device__ fp16 g_Wv16[E_*E_];
__device__ fp16 g_Wvq16[64*E_];
__device__ fp16 g_Wvk16[64*E_];
__device__ fp16 g_Vp[B_*VP_*E_];
__device__ fp16 g_vh[B_*VP_*E_];
__device__ fp16 g_qh[B_*S_*E_];
__device__ fp16 g_kh[B_*S_*E_];
__device__ fp16 g_vqh[B_*S_*VP_];
__device__ fp16 g_vkh[B_*S_*VP_];
__device__ fp16 g_fh[(size_t)B_*S_*S_];   // raw fp16 scores, then softmaxed fp16
__device__ fp16 g_q2b[B_*S_*E_];
__device__ fp16 g_k2b[B_*S_*E_];
__device__ fp16 g_q2h[B_*S_*E_];
__device__ fp16 g_k2h[B_*S_*E_];

// ---------------- PTX helpers ------------------------------------------------
__device__ __forceinline__ uint32_t smem_u32(const void* p) {
    uint32_t a;
    asm("{ .reg .u64 t; cvta.to.shared.u64 t, %1; cvt.u32.u64 %0, t; }"
        : "=r"(a) : "l"(p));
    return a;
}
__device__ __forceinline__ void cp_async16(uint32_t dst, const void* src) {
    asm volatile("cp.async.cg.shared.global [%0], [%1], 16;"
                 :: "r"(dst), "l"(src) : "memory");
}
#define CP_COMMIT() asm volatile("cp.async.commit_group;" ::: "memory")
#define CP_WAIT(n)  asm volatile("cp.async.wait_group %0;" :: "n"(n) : "memory")

#define LDMATRIX_X4(r0, r1, r2, r3, addr) \
    asm volatile("ldmatrix.sync.aligned.m8n8.x4.shared.b16 {%0,%1,%2,%3}, [%4];" \
        : "=r"(r0), "=r"(r1), "=r"(r2), "=r"(r3) : "r"(addr))

#define LDMATRIX_X4_T(r0, r1, r2, r3, addr) \
    asm volatile("ldmatrix.sync.aligned.m8n8.x4.trans.shared.b16 {%0,%1,%2,%3}, [%4];" \
        : "=r"(r0), "=r"(r1), "=r"(r2), "=r"(r3) : "r"(addr))

#define MMA_F16(d, a, b) \
    asm volatile("mma.sync.aligned.m16n8k16.row.col.f32.f16.f16.f32 " \
        "{%0,%1,%2,%3},{%4,%5,%6,%7},{%8,%9},{%0,%1,%2,%3};" \
        : "+f"((d)[0]), "+f"((d)[1]), "+f"((d)[2]), "+f"((d)[3]) \
        : "r"((a)[0]), "r"((a)[1]), "r"((a)[2]), "r"((a)[3]), \
          "r"((b)[0]), "r"((b)[1]))

// ---------------- fp16 HMMA GEMM (NT/NN, paired, fp16 beta-base) -------------
// BK=32, 4-stage cp.async ring, CP_WAIT(2) = 2 tiles in flight (R12 core).
// NT=true : C = alpha * A[M,K] @ B[N,K]^T   (B row-major [N,K])
// NT=false: C = alpha * A[M,K] @ B[K,N]     (B row-major [K,N], ldmatrix.trans)
// BM16: epilogue adds beta * P (fp16). PAIR: blockIdx.z = 2*batch + sel.
constexpr int HM_BM = 128, HM_BN = 128, HM_BK = 32;
constexpr int HM_LDSA = HM_BK + 8;
constexpr int HM_TILEA_B = HM_BM * HM_LDSA * 2; // 10240 bytes (also NT B tile)
constexpr int HM_LDSB = HM_BN + 8;              // NN B row stride (elems)
constexpr int HM_STAGE_B = 20480;
constexpr int HM_SMEM_BYTES = 4 * HM_STAGE_B;   // 81920

template<bool NT, bool BM16, bool PAIR>
__global__ void __launch_bounds__(256, 2)
hmma_g(const fp16* __restrict__ A0, const fp16* __restrict__ A1,
       const fp16* __restrict__ B0, const fp16* __restrict__ B1,
       float* __restrict__ C0, float* __restrict__ C1,
       fp16* __restrict__ O0, fp16* __restrict__ O1,
       const fp16* __restrict__ P0, const fp16* __restrict__ P1,
       const float* __restrict__ bias0, const float* __restrict__ bias1,
       int M, int N, int K, int lda, int ldb, int ldc,
       long long sA, long long sB, long long sC, long long sBias,
       float alpha0, float alpha1, float beta)
{
    extern __shared__ fp16 sm[];
    const uint32_t sbase = smem_u32(sm);

    int sel, zb;
    if (PAIR) { sel = blockIdx.z & 1; zb = blockIdx.z >> 1; }
    else      { sel = 0;              zb = blockIdx.z; }

    const fp16* Ah = (PAIR && sel ? A1 : A0) + (long long)zb * sA;
    const fp16* Bh = (PAIR && sel ? B1 : B0) + (long long)zb * sB;
    float* C  = (PAIR && sel) ? C1 : C0;
    fp16*  Oh = (PAIR && sel) ? O1 : O0;
    const fp16* P = BM16 ? ((PAIR && sel) ? P1 : P0) : nullptr;
    const float* bias = (PAIR && sel) ? bias1 : bias0;
    const float alpha = (PAIR && sel) ? alpha1 : alpha0;
    const long long co = (long long)zb * sC;
    const float* bp = bias ? (bias + (long long)zb * sBias) : nullptr;

    const int tid = threadIdx.x;
    const int warp = tid >> 5, lane = tid & 31;
    const int wm = warp & 3, wn = warp >> 2;         // 4x2 warps: 32m x 64n
    const int bm = blockIdx.y * HM_BM;
    const int bn = blockIdx.x * HM_BN;
    const int NT_ = K / HM_BK;

    const int c0 = tid, c1 = tid + 256;
    const int r0c = c0 >> 2, e0c = (c0 & 3) * 8;
    const int r1c = c1 >> 2, e1c = (c1 & 3) * 8;
    const int rB0 = c0 >> 4, eB0 = (c0 & 15) * 8;
    const int rB1 = c1 >> 4, eB1 = (c1 & 15) * 8;

    auto issue = [&](int it) {
        if (it >= NT_) return;
        const uint32_t sb0 = sbase + (uint32_t)(it & 3) * HM_STAGE_B;
        const long long ko = (long long)it * HM_BK;
        cp_async16(sb0 + (uint32_t)(r0c * HM_LDSA + e0c) * 2,
                   Ah + (long long)(bm + r0c) * lda + ko + e0c);
        cp_async16(sb0 + (uint32_t)(r1c * HM_LDSA + e1c) * 2,
                   Ah + (long long)(bm + r1c) * lda + ko + e1c);
        if (NT) {
            cp_async16(sb0 + HM_TILEA_B + (uint32_t)(r0c * HM_LDSA + e0c) * 2,
                       Bh + (long long)(bn + r0c) * ldb + ko + e0c);
            cp_async16(sb0 + HM_TILEA_B + (uint32_t)(r1c * HM_LDSA + e1c) * 2,
                       Bh + (long long)(bn + r1c) * ldb + ko + e1c);
        } else {
            cp_async16(sb0 + HM_TILEA_B + (uint32_t)(rB0 * HM_LDSB + eB0) * 2,
                       Bh + (ko + rB0) * (long long)ldb + bn + eB0);
            cp_async16(sb0 + HM_TILEA_B + (uint32_t)(rB1 * HM_LDSB + eB1) * 2,
                       Bh + (ko + rB1) * (long long)ldb + bn + eB1);
        }
    };

    float acc[2][8][4];
#pragma unroll
    for (int m = 0; m < 2; m++)
#pragma unroll
        for (int n = 0; n < 8; n++)
#pragma unroll
            for (int j = 0; j < 4; j++) acc[m][n][j] = 0.f;

    issue(0); CP_COMMIT();
    issue(1); CP_COMMIT();
    issue(2); CP_COMMIT();

    const int lr  = lane & 15;
    const int lc8 = (lane >> 4) << 3;

    for (int kt = 0; kt < NT_; ++kt) {
        CP_WAIT(2);
        __syncthreads();                 // single barrier per kt
        issue(kt + 3); CP_COMMIT();      // refill of retired buffer is safe here
        const uint32_t sb0 = sbase + (uint32_t)(kt & 3) * HM_STAGE_B;
#pragma unroll
        for (int ks = 0; ks < 2; ks++) {
            const int k0 = ks * 16;
            uint32_t fA[2][4], fB[8][2];
#pragma unroll
            for (int t = 0; t < 2; t++) {
                uint32_t a = sb0 + (uint32_t)((wm*32 + t*16 + lr) * HM_LDSA + k0 + lc8) * 2;
                LDMATRIX_X4(fA[t][0], fA[t][1], fA[t][2], fA[t][3], a);
            }
            if (NT) {
#pragma unroll
                for (int p = 0; p < 4; p++) {
                    uint32_t a = sb0 + HM_TILEA_B
                               + (uint32_t)((wn*64 + p*16 + lr) * HM_LDSA + k0 + lc8) * 2;
                    uint32_t r0, r1, r2, r3;
                    LDMATRIX_X4(r0, r1, r2, r3, a);
                    fB[p*2][0]   = r0; fB[p*2][1]   = r2;
                    fB[p*2+1][0] = r1; fB[p*2+1][1] = r3;
                }
            } else {
#pragma unroll
                for (int p = 0; p < 4; p++) {
                    uint32_t a = sb0 + HM_TILEA_B
                               + (uint32_t)((k0 + lr) * HM_LDSB + wn*64 + p*16 + lc8) * 2;
                    uint32_t r0, r1, r2, r3;
                    LDMATRIX_X4_T(r0, r1, r2, r3, a);
                    fB[p*2][0]   = r0; fB[p*2][1]   = r1;
                    fB[p*2+1][0] = r2; fB[p*2+1][1] = r3;
                }
            }
#pragma unroll
            for (int m = 0; m < 2; m++)
#pragma unroll
                for (int n = 0; n < 8; n++) MMA_F16(acc[m][n], fA[m], fB[n]);
        }
    }

    // epilogue
    const int qr = lane >> 2, qc = (lane & 3) * 2;
#pragma unroll
    for (int mt = 0; mt < 2; mt++) {
#pragma unroll
        for (int nt = 0; nt < 8; nt++) {
            const int col = bn + wn*64 + nt*8 + qc;
#pragma unroll
            for (int h = 0; h < 2; h++) {
                const int row = bm + wm*32 + mt*16 + qr + h*8;
                const long long o = co + (long long)row * ldc + col;
                float2 v;
                v.x = alpha * acc[mt][nt][h*2 + 0];
                v.y = alpha * acc[mt][nt][h*2 + 1];
                if (BM16) {
                    __half2 pb = *(const __half2*)(P + o);
                    v.x += beta * __half2float(__low2half(pb));
                    v.y += beta * __half2float(__high2half(pb));
                }
                if (bp) { v.x += bp[col]; v.y += bp[col + 1]; }
                if (C)  *(float2*)(C + o) = v;
                if (Oh) *(__half2*)(Oh + o) =
                        __halves2half2(__float2half_rn(v.x), __float2half_rn(v.y));
            }
        }
    }
}

// ---------------- convert kernels --------------------------------------------
template<bool TANH>
__global__ void cvt2_k(const float* __restrict__ x0, const float* __restrict__ x1,
                       fp16* __restrict__ h0, fp16* __restrict__ h1, long long n)
{
    const float* x = blockIdx.y ? x1 : x0;
    fp16* h = blockIdx.y ? h1 : h0;
    long long i = ((long long)blockIdx.x * blockDim.x + threadIdx.x) * 4;
    if (i >= n) return;
    float4 v = *(const float4*)(x + i);
    if (TANH) { v.x = tanhf(v.x); v.y = tanhf(v.y); v.z = tanhf(v.z); v.w = tanhf(v.w); }
    __half2* hp = (__half2*)(h + i);
    hp[0] = __halves2half2(__float2half_rn(v.x), __float2half_rn(v.y));
    hp[1] = __halves2half2(__float2half_rn(v.z), __float2half_rn(v.w));
}

__global__ void cvt3_k(const float* __restrict__ x0, const float* __restrict__ x1,
                       const float* __restrict__ x2,
                       fp16* __restrict__ h0, fp16* __restrict__ h1,
                       fp16* __restrict__ h2, long long n)
{
    const float* x = (blockIdx.y == 0) ? x0 : (blockIdx.y == 1) ? x1 : x2;
    fp16* h = (blockIdx.y == 0) ? h0 : (blockIdx.y == 1) ? h1 : h2;
    long long i = ((long long)blockIdx.x * blockDim.x + threadIdx.x) * 4;
    if (i >= n) return;
    float4 v = *(const float4*)(x + i);
    __half2* hp = (__half2*)(h + i);
    hp[0] = __halves2half2(__float2half_rn(v.x), __float2half_rn(v.y));
    hp[1] = __halves2half2(__float2half_rn(v.z), __float2half_rn(v.w));
}

__global__ void padcvtW2_k(const float* __restrict__ W0, const float* __restrict__ W1,
                           fp16* __restrict__ h0, fp16* __restrict__ h1)
{
    const float* W = blockIdx.y ? W1 : W0;
    fp16* h = blockIdx.y ? h1 : h0;
    long long i = ((long long)blockIdx.x * blockDim.x + threadIdx.x) * 4;
    if (i >= 64 * E_) return;
    int r = (int)(i / E_), e = (int)(i % E_);
    float4 v = make_float4(0.f, 0.f, 0.f, 0.f);
    if (r < SV_) v = *(const float4*)(W + (long long)r * E_ + e);
    __half2* hp = (__half2*)(h + i);
    hp[0] = __halves2half2(__float2half_rn(v.x), __float2half_rn(v.y));
    hp[1] = __halves2half2(__float2half_rn(v.z), __float2half_rn(v.w));
}

__global__ void padcvtV_k(const float* __restrict__ V, fp16* __restrict__ h)
{
    long long i = ((long long)blockIdx.x * blockDim.x + threadIdx.x) * 4;
    if (i >= (long long)B_ * VP_ * E_) return;
    int b = (int)(i / (VP_ * E_));
    int rem = (int)(i % (VP_ * E_));
    int r = rem / E_, e = rem % E_;
    float4 v = make_float4(0.f, 0.f, 0.f, 0.f);
    if (r < SV_) {
        v = *(const float4*)(V + ((long long)(b * SV_ + r)) * E_ + e);
        v.x = tanhf(v.x); v.y = tanhf(v.y); v.z = tanhf(v.z); v.w = tanhf(v.w);
    }
    __half2* hp = (__half2*)(h + i);
    hp[0] = __halves2half2(__float2half_rn(v.x), __float2half_rn(v.y));
    hp[1] = __halves2half2(__float2half_rn(v.z), __float2half_rn(v.w));
}

// ---------------- softmax: fp16 scores in-place -> fp32 f + fp16 fh ----------
// cols must equal 8*256 = 2048
__global__ void softmax_cvt(fp16* __restrict__ h, float* __restrict__ x, int cols)
{
    long long r = blockIdx.x;
    fp16* hp = h + r * (long long)cols;
    float* p = x + r * (long long)cols;
    __shared__ float red[256];
    const int t = threadIdx.x;

    float vals[8];
#pragma unroll
    for (int i = 0; i < 8; i++) vals[i] = __half2float(hp[t + i * 256]);

    float mx = vals[0];
#pragma unroll
    for (int i = 1; i < 8; i++) mx = fmaxf(mx, vals[i]);
    red[t] = mx; __syncthreads();
    for (int s = 128; s > 0; s >>= 1) { if (t < s) red[t] = fmaxf(red[t], red[t + s]); __syncthreads(); }
    mx = red[0]; __syncthreads();

    float sum = 0.f;
#pragma unroll
    for (int i = 0; i < 8; i++) { vals[i] = expf(vals[i] - mx); sum += vals[i]; }
    red[t] = sum; __syncthreads();
    for (int s = 128; s > 0; s >>= 1) { if (t < s) red[t] += red[t + s]; __syncthreads(); }
    const float inv = 1.f / red[0];

#pragma unroll
    for (int i = 0; i < 8; i++) {
        float val = vals[i] * inv;
        p[t + i * 256] = val;
        hp[t + i * 256] = __float2half_rn(val);
    }
}

// colsum over fp16 input
__global__ void colsum16_k(const fp16* __restrict__ x, float* __restrict__ out,
                           int T, int E)
{
    int e = blockIdx.x * blockDim.x + threadIdx.x;
    int b = blockIdx.y;
    const fp16* p = x + (long long)b * T * E + e;
    float s = 0.f;
    for (int t = 0; t < T; t++) s += __half2float(p[(long long)t * E]);
    out[(long long)b * E + e] = s;
}

// ---------------- host launcher ----------------------------------------------
extern "C" void kernel_launch(void* const* d_in, const int* in_sizes, int n_in,
                              void* d_out, int out_size)
{
    const float* Q    = (const float*)d_in[0];
    const float* K    = (const float*)d_in[1];
    const float* V    = (const float*)d_in[2];
    const float* W_Q  = (const float*)d_in[3];
    const float* W_K  = (const float*)d_in[4];
    const float* W_v  = (const float*)d_in[5];
    const float* W_vq = (const float*)d_in[6];
    const float* W_vk = (const float*)d_in[7];

    float* out  = (float*)d_out;
    float* outQ = out;
    float* outK = out + (long long)B_ * S_ * E_;
    float* f    = out + 2ll * B_ * S_ * E_;

    float *cs, *cs2;
    cudaGetSymbolAddress((void**)&cs,  g_cs);
    cudaGetSymbolAddress((void**)&cs2, g_cs2);

    fp16 *Qs,*Ks,*Wq16,*Wk16,*Wv16,*Wvq16,*Wvk16,*Vp,*vh;
    fp16 *qh,*kh,*vqh,*vkh,*fh,*q2b,*k2b,*q2h,*k2h;
    cudaGetSymbolAddress((void**)&Qs,    g_Qs);
    cudaGetSymbolAddress((void**)&Ks,    g_Ks);
    cudaGetSymbolAddress((void**)&Wq16,  g_Wq16);
    cudaGetSymbolAddress((void**)&Wk16,  g_Wk16);
    cudaGetSymbolAddress((void**)&Wv16,  g_Wv16);
    cudaGetSymbolAddress((void**)&Wvq16, g_Wvq16);
    cudaGetSymbolAddress((void**)&Wvk16, g_Wvk16);
    cudaGetSymbolAddress((void**)&Vp,    g_Vp);
    cudaGetSymbolAddress((void**)&vh,    g_vh);
    cudaGetSymbolAddress((void**)&qh,    g_qh);
    cudaGetSymbolAddress((void**)&kh,    g_kh);
    cudaGetSymbolAddress((void**)&vqh,   g_vqh);
    cudaGetSymbolAddress((void**)&vkh,   g_vkh);
    cudaGetSymbolAddress((void**)&fh,    g_fh);
    cudaGetSymbolAddress((void**)&q2b,   g_q2b);
    cudaGetSymbolAddress((void**)&k2b,   g_k2b);
    cudaGetSymbolAddress((void**)&q2h,   g_q2h);
    cudaGetSymbolAddress((void**)&k2h,   g_k2h);

    cudaFuncSetAttribute(hmma_g<false,false,false>, cudaFuncAttributeMaxDynamicSharedMemorySize, HM_SMEM_BYTES);
    cudaFuncSetAttribute(hmma_g<false,false,true >, cudaFuncAttributeMaxDynamicSharedMemorySize, HM_SMEM_BYTES);
    cudaFuncSetAttribute(hmma_g<true ,false,false>, cudaFuncAttributeMaxDynamicSharedMemorySize, HM_SMEM_BYTES);
    cudaFuncSetAttribute(hmma_g<true ,false,true >, cudaFuncAttributeMaxDynamicSharedMemorySize, HM_SMEM_BYTES);
    cudaFuncSetAttribute(hmma_g<false,true ,true >, cudaFuncAttributeMaxDynamicSharedMemorySize, HM_SMEM_BYTES);

    const float inv = 1.0f / 32.0f;  // 1/sqrt(1024)
    const long long sQE = (long long)S_ * E_;
    const long long sSS = (long long)S_ * S_;
    const long long sVE = (long long)VP_ * E_;
    const long long sSV = (long long)S_ * VP_;
    const long long nQE = (long long)B_ * S_ * E_;

    // ---- stage 0: input conversions ----------------------------------------
    cvt2_k<true><<<dim3((int)(nQE/4/256), 2), 256>>>(Q, K, Qs, Ks, nQE);
    cvt3_k<<<dim3((int)((long long)E_*E_/4/256), 3), 256>>>(
        W_Q, W_K, W_v, Wq16, Wk16, Wv16, (long long)E_*E_);
    padcvtW2_k<<<dim3(64, 2), 256>>>(W_vq, W_vk, Wvq16, Wvk16);
    padcvtV_k<<<(int)((long long)B_*VP_*E_/4/256), 256>>>(V, Vp);

    // ---- stage 1: paired Q/K projections (NN, fp16 out only) + v -----------
    hmma_g<false,false,true><<<dim3(8,64,2), 256, HM_SMEM_BYTES>>>(
        Qs, Ks, Wq16, Wk16, nullptr, nullptr, qh, kh, nullptr, nullptr,
        nullptr, nullptr,
        B_*S_, E_, E_, E_, E_, E_, 0,0,0,0, 1.f, 1.f, 0.f);
    hmma_g<false,false,false><<<dim3(8,(B_*VP_)/128,1), 256, HM_SMEM_BYTES>>>(
        Vp, nullptr, Wv16, nullptr, nullptr, nullptr, vh, nullptr, nullptr, nullptr,
        nullptr, nullptr,
        B_*VP_, E_, E_, E_, E_, E_, 0,0,0,0, 1.f, 0.f, 0.f);

    colsum16_k<<<dim3(E_/256,B_), 256>>>(kh, cs, S_, E_);

    // ---- stage 3: raw fp16 scores -> softmax (writes fp32 f + fp16 fh) -----
    hmma_g<true,false,false><<<dim3(16,16,B_), 256, HM_SMEM_BYTES>>>(
        qh, nullptr, kh, nullptr, nullptr, nullptr, fh, nullptr, nullptr, nullptr,
        nullptr, nullptr,
        S_, S_, E_, E_, E_, S_, sQE, sQE, sSS, 0, inv, 0.f, 0.f);
    softmax_cvt<<<B_*S_, 256>>>(fh, f, S_);

    // ---- vq/vk paired (NT, N=VP=128) + q2/k2 base paired (NN) --------------
    hmma_g<true,false,true><<<dim3(VP_/128,16,2*B_), 256, HM_SMEM_BYTES>>>(
        qh, kh, vh, vh, nullptr, nullptr, vqh, vkh, nullptr, nullptr,
        nullptr, nullptr,
        S_, VP_, E_, E_, E_, VP_, sQE, sVE, sSV, 0, inv, inv, 0.f);
    hmma_g<false,false,true><<<dim3(8,16,2*B_), 256, HM_SMEM_BYTES>>>(
        vqh, vkh, Wvq16, Wvk16, nullptr, nullptr, q2b, k2b, nullptr, nullptr,
        nullptr, cs,
        S_, E_, 64, VP_, E_, E_, sSV, 0, sQE, E_, 1.f, 1.f, 0.f);

    // ---- stage 4: q2 = f@q + q2b ; k2 = -(f@k) + k2b (fp16 base + out) -----
    hmma_g<false,true,true><<<dim3(8,16,2*B_), 256, HM_SMEM_BYTES>>>(
        fh, fh, qh, kh, nullptr, nullptr, q2h, k2h, q2b, k2b,
        nullptr, nullptr,
        S_, E_, S_, S_, E_, E_, sSS, sQE, sQE, 0, 1.f, -1.f, 1.f);

    colsum16_k<<<dim3(E_/256,B_), 256>>>(k2h, cs2, S_, E_);

    // ---- stage 5: outputs (paired NN) --------------------------------------
    hmma_g<false,false,true><<<dim3(8,16,2*B_), 256, HM_SMEM_BYTES>>>(
        fh, fh, q2h, k2h, outQ, outK, nullptr, nullptr, nullptr, nullptr,
        nullptr, cs2,
        S_, E_, S_, S_, E_, E_, sSS, sQE, sQE, E_, 1.f, -1.f, 0.f);

    (void)in_sizes; (void)n_in; (void)out_size;
}

// round 15
// speedup vs baseline: 1.2205x; 1.0089x over previous
#include <cuda_runtime.h>
#include <cuda_fp16.h>
#include <math.h>
#include <stdint.h>

#define B_  4
#define S_  2048
#define SV_ 50
#define E_  1024
#define VP_ 128   // padded v rows per batch

typedef __half fp16;

// ---------------- scratch (device globals) ----------------------------------
__device__ float g_cs [B_*E_];
__device__ float g_cs2[B_*E_];

__device__ fp16 g_Qs[B_*S_*E_];
__device__ fp16 g_Ks[B_*S_*E_];
__device__ fp16 g_Wq16[E_*E_];
__device__ fp16 g_Wk16[E_*E_];
__device__ fp16 g_Wv16[E_*E_];
__device__ fp16 g_Wvq16[64*E_];
__device__ fp16 g_Wvk16[64*E_];
__device__ fp16 g_Vp[B_*VP_*E_];
__device__ fp16 g_vh[B_*VP_*E_];
__device__ fp16 g_qh[B_*S_*E_];
__device__ fp16 g_kh[B_*S_*E_];
__device__ fp16 g_vqh[B_*S_*VP_];
__device__ fp16 g_vkh[B_*S_*VP_];
__device__ fp16 g_fh[(size_t)B_*S_*S_];   // raw fp16 scores, then softmaxed fp16
__device__ fp16 g_q2b[B_*S_*E_];
__device__ fp16 g_k2b[B_*S_*E_];
__device__ fp16 g_q2h[B_*S_*E_];
__device__ fp16 g_k2h[B_*S_*E_];

// ---------------- PTX helpers ------------------------------------------------
__device__ __forceinline__ uint32_t smem_u32(const void* p) {
    uint32_t a;
    asm("{ .reg .u64 t; cvta.to.shared.u64 t, %1; cvt.u32.u64 %0, t; }"
        : "=r"(a) : "l"(p));
    return a;
}
__device__ __forceinline__ void cp_async16(uint32_t dst, const void* src) {
    asm volatile("cp.async.cg.shared.global [%0], [%1], 16;"
                 :: "r"(dst), "l"(src) : "memory");
}
#define CP_COMMIT() asm volatile("cp.async.commit_group;" ::: "memory")
#define CP_WAIT(n)  asm volatile("cp.async.wait_group %0;" :: "n"(n) : "memory")

#define LDMATRIX_X4(r0, r1, r2, r3, addr) \
    asm volatile("ldmatrix.sync.aligned.m8n8.x4.shared.b16 {%0,%1,%2,%3}, [%4];" \
        : "=r"(r0), "=r"(r1), "=r"(r2), "=r"(r3) : "r"(addr))

#define LDMATRIX_X4_T(r0, r1, r2, r3, addr) \
    asm volatile("ldmatrix.sync.aligned.m8n8.x4.trans.shared.b16 {%0,%1,%2,%3}, [%4];" \
        : "=r"(r0), "=r"(r1), "=r"(r2), "=r"(r3) : "r"(addr))

#define MMA_F16(d, a, b) \
    asm volatile("mma.sync.aligned.m16n8k16.row.col.f32.f16.f16.f32 " \
        "{%0,%1,%2,%3},{%4,%5,%6,%7},{%8,%9},{%0,%1,%2,%3};" \
        : "+f"((d)[0]), "+f"((d)[1]), "+f"((d)[2]), "+f"((d)[3]) \
        : "r"((a)[0]), "r"((a)[1]), "r"((a)[2]), "r"((a)[3]), \
          "r"((b)[0]), "r"((b)[1]))

// ---------------- fp16 HMMA GEMM (NT/NN, paired, fp16 beta-base) -------------
// BK=32, 5-stage cp.async ring, CP_WAIT(3) = 3 complete tiles in flight.
// NT=true : C = alpha * A[M,K] @ B[N,K]^T   (B row-major [N,K])
// NT=false: C = alpha * A[M,K] @ B[K,N]     (B row-major [K,N], ldmatrix.trans)
// BM16: epilogue adds beta * P (fp16). PAIR: blockIdx.z = 2*batch + sel.
constexpr int HM_BM = 128, HM_BN = 128, HM_BK = 32;
constexpr int HM_LDSA = HM_BK + 8;
constexpr int HM_TILEA_B = HM_BM * HM_LDSA * 2; // 10240 bytes (also NT B tile)
constexpr int HM_LDSB = HM_BN + 8;              // NN B row stride (elems)
constexpr int HM_STAGE_B = 20480;
constexpr int HM_NSTAGE = 5;
constexpr int HM_SMEM_BYTES = HM_NSTAGE * HM_STAGE_B;   // 102400

template<bool NT, bool BM16, bool PAIR>
__global__ void __launch_bounds__(256, 2)
hmma_g(const fp16* __restrict__ A0, const fp16* __restrict__ A1,
       const fp16* __restrict__ B0, const fp16* __restrict__ B1,
       float* __restrict__ C0, float* __restrict__ C1,
       fp16* __restrict__ O0, fp16* __restrict__ O1,
       const fp16* __restrict__ P0, const fp16* __restrict__ P1,
       const float* __restrict__ bias0, const float* __restrict__ bias1,
       int M, int N, int K, int lda, int ldb, int ldc,
       long long sA, long long sB, long long sC, long long sBias,
       float alpha0, float alpha1, float beta)
{
    extern __shared__ fp16 sm[];
    const uint32_t sbase = smem_u32(sm);

    int sel, zb;
    if (PAIR) { sel = blockIdx.z & 1; zb = blockIdx.z >> 1; }
    else      { sel = 0;              zb = blockIdx.z; }

    const fp16* Ah = (PAIR && sel ? A1 : A0) + (long long)zb * sA;
    const fp16* Bh = (PAIR && sel ? B1 : B0) + (long long)zb * sB;
    float* C  = (PAIR && sel) ? C1 : C0;
    fp16*  Oh = (PAIR && sel) ? O1 : O0;
    const fp16* P = BM16 ? ((PAIR && sel) ? P1 : P0) : nullptr;
    const float* bias = (PAIR && sel) ? bias1 : bias0;
    const float alpha = (PAIR && sel) ? alpha1 : alpha0;
    const long long co = (long long)zb * sC;
    const float* bp = bias ? (bias + (long long)zb * sBias) : nullptr;

    const int tid = threadIdx.x;
    const int warp = tid >> 5, lane = tid & 31;
    const int wm = warp & 3, wn = warp >> 2;         // 4x2 warps: 32m x 64n
    const int bm = blockIdx.y * HM_BM;
    const int bn = blockIdx.x * HM_BN;
    const int NT_ = K / HM_BK;

    const int c0 = tid, c1 = tid + 256;
    const int r0c = c0 >> 2, e0c = (c0 & 3) * 8;
    const int r1c = c1 >> 2, e1c = (c1 & 3) * 8;
    const int rB0 = c0 >> 4, eB0 = (c0 & 15) * 8;
    const int rB1 = c1 >> 4, eB1 = (c1 & 15) * 8;

    auto issue = [&](int it) {
        if (it >= NT_) return;
        const uint32_t sb0 = sbase + (uint32_t)(it % HM_NSTAGE) * HM_STAGE_B;
        const long long ko = (long long)it * HM_BK;
        cp_async16(sb0 + (uint32_t)(r0c * HM_LDSA + e0c) * 2,
                   Ah + (long long)(bm + r0c) * lda + ko + e0c);
        cp_async16(sb0 + (uint32_t)(r1c * HM_LDSA + e1c) * 2,
                   Ah + (long long)(bm + r1c) * lda + ko + e1c);
        if (NT) {
            cp_async16(sb0 + HM_TILEA_B + (uint32_t)(r0c * HM_LDSA + e0c) * 2,
                       Bh + (long long)(bn + r0c) * ldb + ko + e0c);
            cp_async16(sb0 + HM_TILEA_B + (uint32_t)(r1c * HM_LDSA + e1c) * 2,
                       Bh + (long long)(bn + r1c) * ldb + ko + e1c);
        } else {
            cp_async16(sb0 + HM_TILEA_B + (uint32_t)(rB0 * HM_LDSB + eB0) * 2,
                       Bh + (ko + rB0) * (long long)ldb + bn + eB0);
            cp_async16(sb0 + HM_TILEA_B + (uint32_t)(rB1 * HM_LDSB + eB1) * 2,
                       Bh + (ko + rB1) * (long long)ldb + bn + eB1);
        }
    };

    float acc[2][8][4];
#pragma unroll
    for (int m = 0; m < 2; m++)
#pragma unroll
        for (int n = 0; n < 8; n++)
#pragma unroll
            for (int j = 0; j < 4; j++) acc[m][n][j] = 0.f;

    issue(0); CP_COMMIT();
    issue(1); CP_COMMIT();
    issue(2); CP_COMMIT();
    issue(3); CP_COMMIT();

    const int lr  = lane & 15;
    const int lc8 = (lane >> 4) << 3;

    for (int kt = 0; kt < NT_; ++kt) {
        CP_WAIT(3);                      // tile kt complete; 3 newer in flight
        __syncthreads();                 // single barrier per kt
        issue(kt + 4); CP_COMMIT();      // refills buffer (kt-1)%5, retired at barrier
        const uint32_t sb0 = sbase + (uint32_t)(kt % HM_NSTAGE) * HM_STAGE_B;
#pragma unroll
        for (int ks = 0; ks < 2; ks++) {
            const int k0 = ks * 16;
            uint32_t fA[2][4], fB[8][2];
#pragma unroll
            for (int t = 0; t < 2; t++) {
                uint32_t a = sb0 + (uint32_t)((wm*32 + t*16 + lr) * HM_LDSA + k0 + lc8) * 2;
                LDMATRIX_X4(fA[t][0], fA[t][1], fA[t][2], fA[t][3], a);
            }
            if (NT) {
#pragma unroll
                for (int p = 0; p < 4; p++) {
                    uint32_t a = sb0 + HM_TILEA_B
                               + (uint32_t)((wn*64 + p*16 + lr) * HM_LDSA + k0 + lc8) * 2;
                    uint32_t r0, r1, r2, r3;
                    LDMATRIX_X4(r0, r1, r2, r3, a);
                    fB[p*2][0]   = r0; fB[p*2][1]   = r2;
                    fB[p*2+1][0] = r1; fB[p*2+1][1] = r3;
                }
            } else {
#pragma unroll
                for (int p = 0; p < 4; p++) {
                    uint32_t a = sb0 + HM_TILEA_B
                               + (uint32_t)((k0 + lr) * HM_LDSB + wn*64 + p*16 + lc8) * 2;
                    uint32_t r0, r1, r2, r3;
                    LDMATRIX_X4_T(r0, r1, r2, r3, a);
                    fB[p*2][0]   = r0; fB[p*2][1]   = r1;
                    fB[p*2+1][0] = r2; fB[p*2+1][1] = r3;
                }
            }
#pragma unroll
            for (int m = 0; m < 2; m++)
#pragma unroll
                for (int n = 0; n < 8; n++) MMA_F16(acc[m][n], fA[m], fB[n]);
        }
    }

    // epilogue
    const int qr = lane >> 2, qc = (lane & 3) * 2;
#pragma unroll
    for (int mt = 0; mt < 2; mt++) {
#pragma unroll
        for (int nt = 0; nt < 8; nt++) {
            const int col = bn + wn*64 + nt*8 + qc;
#pragma unroll
            for (int h = 0; h < 2; h++) {
                const int row = bm + wm*32 + mt*16 + qr + h*8;
                const long long o = co + (long long)row * ldc + col;
                float2 v;
                v.x = alpha * acc[mt][nt][h*2 + 0];
                v.y = alpha * acc[mt][nt][h*2 + 1];
                if (BM16) {
                    __half2 pb = *(const __half2*)(P + o);
                    v.x += beta * __half2float(__low2half(pb));
                    v.y += beta * __half2float(__high2half(pb));
                }
                if (bp) { v.x += bp[col]; v.y += bp[col + 1]; }
                if (C)  *(float2*)(C + o) = v;
                if (Oh) *(__half2*)(Oh + o) =
                        __halves2half2(__float2half_rn(v.x), __float2half_rn(v.y));
            }
        }
    }
}

// ---------------- convert kernels --------------------------------------------
template<bool TANH>
__global__ void cvt2_k(const float* __restrict__ x0, const float* __restrict__ x1,
                       fp16* __restrict__ h0, fp16* __restrict__ h1, long long n)
{
    const float* x = blockIdx.y ? x1 : x0;
    fp16* h = blockIdx.y ? h1 : h0;
    long long i = ((long long)blockIdx.x * blockDim.x + threadIdx.x) * 4;
    if (i >= n) return;
    float4 v = *(const float4*)(x + i);
    if (TANH) { v.x = tanhf(v.x); v.y = tanhf(v.y); v.z = tanhf(v.z); v.w = tanhf(v.w); }
    __half2* hp = (__half2*)(h + i);
    hp[0] = __halves2half2(__float2half_rn(v.x), __float2half_rn(v.y));
    hp[1] = __halves2half2(__float2half_rn(v.z), __float2half_rn(v.w));
}

__global__ void cvt3_k(const float* __restrict__ x0, const float* __restrict__ x1,
                       const float* __restrict__ x2,
                       fp16* __restrict__ h0, fp16* __restrict__ h1,
                       fp16* __restrict__ h2, long long n)
{
    const float* x = (blockIdx.y == 0) ? x0 : (blockIdx.y == 1) ? x1 : x2;
    fp16* h = (blockIdx.y == 0) ? h0 : (blockIdx.y == 1) ? h1 : h2;
    long long i = ((long long)blockIdx.x * blockDim.x + threadIdx.x) * 4;
    if (i >= n) return;
    float4 v = *(const float4*)(x + i);
    __half2* hp = (__half2*)(h + i);
    hp[0] = __halves2half2(__float2half_rn(v.x), __float2half_rn(v.y));
    hp[1] = __halves2half2(__float2half_rn(v.z), __float2half_rn(v.w));
}

__global__ void padcvtW2_k(const float* __restrict__ W0, const float* __restrict__ W1,
                           fp16* __restrict__ h0, fp16* __restrict__ h1)
{
    const float* W = blockIdx.y ? W1 : W0;
    fp16* h = blockIdx.y ? h1 : h0;
    long long i = ((long long)blockIdx.x * blockDim.x + threadIdx.x) * 4;
    if (i >= 64 * E_) return;
    int r = (int)(i / E_), e = (int)(i % E_);
    float4 v = make_float4(0.f, 0.f, 0.f, 0.f);
    if (r < SV_) v = *(const float4*)(W + (long long)r * E_ + e);
    __half2* hp = (__half2*)(h + i);
    hp[0] = __halves2half2(__float2half_rn(v.x), __float2half_rn(v.y));
    hp[1] = __halves2half2(__float2half_rn(v.z), __float2half_rn(v.w));
}

__global__ void padcvtV_k(const float* __restrict__ V, fp16* __restrict__ h)
{
    long long i = ((long long)blockIdx.x * blockDim.x + threadIdx.x) * 4;
    if (i >= (long long)B_ * VP_ * E_) return;
    int b = (int)(i / (VP_ * E_));
    int rem = (int)(i % (VP_ * E_));
    int r = rem / E_, e = rem % E_;
    float4 v = make_float4(0.f, 0.f, 0.f, 0.f);
    if (r < SV_) {
        v = *(const float4*)(V + ((long long)(b * SV_ + r)) * E_ + e);
        v.x = tanhf(v.x); v.y = tanhf(v.y); v.z = tanhf(v.z); v.w = tanhf(v.w);
    }
    __half2* hp = (__half2*)(h + i);
    hp[0] = __halves2half2(__float2half_rn(v.x), __float2half_rn(v.y));
    hp[1] = __halves2half2(__float2half_rn(v.z), __float2half_rn(v.w));
}

// ---------------- softmax: fp16 scores in-place -> fp32 f + fp16 fh ----------
// cols must equal 8*256 = 2048
__global__ void softmax_cvt(fp16* __restrict__ h, float* __restrict__ x, int cols)
{
    long long r = blockIdx.x;
    fp16* hp = h + r * (long long)cols;
    float* p = x + r * (long long)cols;
    __shared__ float red[256];
    const int t = threadIdx.x;

    float vals[8];
#pragma unroll
    for (int i = 0; i < 8; i++) vals[i] = __half2float(hp[t + i * 256]);

    float mx = vals[0];
#pragma unroll
    for (int i = 1; i < 8; i++) mx = fmaxf(mx, vals[i]);
    red[t] = mx; __syncthreads();
    for (int s = 128; s > 0; s >>= 1) { if (t < s) red[t] = fmaxf(red[t], red[t + s]); __syncthreads(); }
    mx = red[0]; __syncthreads();

    float sum = 0.f;
#pragma unroll
    for (int i = 0; i < 8; i++) { vals[i] = expf(vals[i] - mx); sum += vals[i]; }
    red[t] = sum; __syncthreads();
    for (int s = 128; s > 0; s >>= 1) { if (t < s) red[t] += red[t + s]; __syncthreads(); }
    const float inv = 1.f / red[0];

#pragma unroll
    for (int i = 0; i < 8; i++) {
        float val = vals[i] * inv;
        p[t + i * 256] = val;
        hp[t + i * 256] = __float2half_rn(val);
    }
}

// colsum over fp16 input
__global__ void colsum16_k(const fp16* __restrict__ x, float* __restrict__ out,
                           int T, int E)
{
    int e = blockIdx.x * blockDim.x + threadIdx.x;
    int b = blockIdx.y;
    const fp16* p = x + (long long)b * T * E + e;
    float s = 0.f;
    for (int t = 0; t < T; t++) s += __half2float(p[(long long)t * E]);
    out[(long long)b * E + e] = s;
}

// ---------------- host launcher ----------------------------------------------
extern "C" void kernel_launch(void* const* d_in, const int* in_sizes, int n_in,
                              void* d_out, int out_size)
{
    const float* Q    = (const float*)d_in[0];
    const float* K    = (const float*)d_in[1];
    const float* V    = (const float*)d_in[2];
    const float* W_Q  = (const float*)d_in[3];
    const float* W_K  = (const float*)d_in[4];
    const float* W_v  = (const float*)d_in[5];
    const float* W_vq = (const float*)d_in[6];
    const float* W_vk = (const float*)d_in[7];

    float* out  = (float*)d_out;
    float* outQ = out;
    float* outK = out + (long long)B_ * S_ * E_;
    float* f    = out + 2ll * B_ * S_ * E_;

    float *cs, *cs2;
    cudaGetSymbolAddress((void**)&cs,  g_cs);
    cudaGetSymbolAddress((void**)&cs2, g_cs2);

    fp16 *Qs,*Ks,*Wq16,*Wk16,*Wv16,*Wvq16,*Wvk16,*Vp,*vh;
    fp16 *qh,*kh,*vqh,*vkh,*fh,*q2b,*k2b,*q2h,*k2h;
    cudaGetSymbolAddress((void**)&Qs,    g_Qs);
    cudaGetSymbolAddress((void**)&Ks,    g_Ks);
    cudaGetSymbolAddress((void**)&Wq16,  g_Wq16);
    cudaGetSymbolAddress((void**)&Wk16,  g_Wk16);
    cudaGetSymbolAddress((void**)&Wv16,  g_Wv16);
    cudaGetSymbolAddress((void**)&Wvq16, g_Wvq16);
    cudaGetSymbolAddress((void**)&Wvk16, g_Wvk16);
    cudaGetSymbolAddress((void**)&Vp,    g_Vp);
    cudaGetSymbolAddress((void**)&vh,    g_vh);
    cudaGetSymbolAddress((void**)&qh,    g_qh);
    cudaGetSymbolAddress((void**)&kh,    g_kh);
    cudaGetSymbolAddress((void**)&vqh,   g_vqh);
    cudaGetSymbolAddress((void**)&vkh,   g_vkh);
    cudaGetSymbolAddress((void**)&fh,    g_fh);
    cudaGetSymbolAddress((void**)&q2b,   g_q2b);
    cudaGetSymbolAddress((void**)&k2b,   g_k2b);
    cudaGetSymbolAddress((void**)&q2h,   g_q2h);
    cudaGetSymbolAddress((void**)&k2h,   g_k2h);

    cudaFuncSetAttribute(hmma_g<false,false,false>, cudaFuncAttributeMaxDynamicSharedMemorySize, HM_SMEM_BYTES);
    cudaFuncSetAttribute(hmma_g<false,false,true >, cudaFuncAttributeMaxDynamicSharedMemorySize, HM_SMEM_BYTES);
    cudaFuncSetAttribute(hmma_g<true ,false,false>, cudaFuncAttributeMaxDynamicSharedMemorySize, HM_SMEM_BYTES);
    cudaFuncSetAttribute(hmma_g<true ,false,true >, cudaFuncAttributeMaxDynamicSharedMemorySize, HM_SMEM_BYTES);
    cudaFuncSetAttribute(hmma_g<false,true ,true >, cudaFuncAttributeMaxDynamicSharedMemorySize, HM_SMEM_BYTES);

    const float inv = 1.0f / 32.0f;  // 1/sqrt(1024)
    const long long sQE = (long long)S_ * E_;
    const long long sSS = (long long)S_ * S_;
    const long long sVE = (long long)VP_ * E_;
    const long long sSV = (long long)S_ * VP_;
    const long long nQE = (long long)B_ * S_ * E_;

    // ---- stage 0: input conversions ----------------------------------------
    cvt2_k<true><<<dim3((int)(nQE/4/256), 2), 256>>>(Q, K, Qs, Ks, nQE);
    cvt3_k<<<dim3((int)((long long)E_*E_/4/256), 3), 256>>>(
        W_Q, W_K, W_v, Wq16, Wk16, Wv16, (long long)E_*E_);
    padcvtW2_k<<<dim3(64, 2), 256>>>(W_vq, W_vk, Wvq16, Wvk16);
    padcvtV_k<<<(int)((long long)B_*VP_*E_/4/256), 256>>>(V, Vp);

    // ---- stage 1: paired Q/K projections (NN, fp16 out only) + v -----------
    hmma_g<false,false,true><<<dim3(8,64,2), 256, HM_SMEM_BYTES>>>(
        Qs, Ks, Wq16, Wk16, nullptr, nullptr, qh, kh, nullptr, nullptr,
        nullptr, nullptr,
        B_*S_, E_, E_, E_, E_, E_, 0,0,0,0, 1.f, 1.f, 0.f);
    hmma_g<false,false,false><<<dim3(8,(B_*VP_)/128,1), 256, HM_SMEM_BYTES>>>(
        Vp, nullptr, Wv16, nullptr, nullptr, nullptr, vh, nullptr, nullptr, nullptr,
        nullptr, nullptr,
        B_*VP_, E_, E_, E_, E_, E_, 0,0,0,0, 1.f, 0.f, 0.f);

    colsum16_k<<<dim3(E_/256,B_), 256>>>(kh, cs, S_, E_);

    // ---- stage 3: raw fp16 scores -> softmax (writes fp32 f + fp16 fh) -----
    hmma_g<true,false,false><<<dim3(16,16,B_), 256, HM_SMEM_BYTES>>>(
        qh, nullptr, kh, nullptr, nullptr, nullptr, fh, nullptr, nullptr, nullptr,
        nullptr, nullptr,
        S_, S_, E_, E_, E_, S_, sQE, sQE, sSS, 0, inv, 0.f, 0.f);
    softmax_cvt<<<B_*S_, 256>>>(fh, f, S_);

    // ---- vq/vk paired (NT, N=VP=128) + q2/k2 base paired (NN) --------------
    hmma_g<true,false,true><<<dim3(VP_/128,16,2*B_), 256, HM_SMEM_BYTES>>>(
        qh, kh, vh, vh, nullptr, nullptr, vqh, vkh, nullptr, nullptr,
        nullptr, nullptr,
        S_, VP_, E_, E_, E_, VP_, sQE, sVE, sSV, 0, inv, inv, 0.f);
    hmma_g<false,false,true><<<dim3(8,16,2*B_), 256, HM_SMEM_BYTES>>>(
        vqh, vkh, Wvq16, Wvk16, nullptr, nullptr, q2b, k2b, nullptr, nullptr,
        nullptr, cs,
        S_, E_, 64, VP_, E_, E_, sSV, 0, sQE, E_, 1.f, 1.f, 0.f);

    // ---- stage 4: q2 = f@q + q2b ; k2 = -(f@k) + k2b (fp16 base + out) -----
    hmma_g<false,true,true><<<dim3(8,16,2*B_), 256, HM_SMEM_BYTES>>>(
        fh, fh, qh, kh, nullptr, nullptr, q2h, k2h, q2b, k2b,
        nullptr, nullptr,
        S_, E_, S_, S_, E_, E_, sSS, sQE, sQE, 0, 1.f, -1.f, 1.f);

    colsum16_k<<<dim3(E_/256,B_), 256>>>(k2h, cs2, S_, E_);

    // ---- stage 5: outputs (paired NN) --------------------------------------
    hmma_g<false,false,true><<<dim3(8,16,2*B_), 256, HM_SMEM_BYTES>>>(
        fh, fh, q2h, k2h, outQ, outK, nullptr, nullptr, nullptr, nullptr,
        nullptr, cs2,
        S_, E_, S_, S_, E_, E_, sSS, sQE, sQE, E_, 1.f, -1.f, 0.f);

    (void)in_sizes; (void)n_in; (void)out_size;
}

// round 16
// speedup vs baseline: 1.7362x; 1.4226x over previous
#include <cuda_runtime.h>
#include <cuda_fp16.h>
#include <math.h>
#include <stdint.h>

#define B_  4
#define S_  2048
#define SV_ 50
#define E_  1024
#define VP_ 128   // padded v rows per batch
#define CSCH 32   // colsum chunks

typedef __half fp16;

// ---------------- scratch (device globals) ----------------------------------
__device__ float g_cs [B_*E_];
__device__ float g_cs2[B_*E_];
__device__ float g_part[CSCH*B_*E_];

__device__ fp16 g_Qs[B_*S_*E_];
__device__ fp16 g_Ks[B_*S_*E_];
__device__ fp16 g_Wq16[E_*E_];
__device__ fp16 g_Wk16[E_*E_];
__device__ fp16 g_Wv16[E_*E_];
__device__ fp16 g_Wvq16[64*E_];
__device__ fp16 g_Wvk16[64*E_];
__device__ fp16 g_Vp[B_*VP_*E_];
__device__ fp16 g_vh[B_*VP_*E_];
__device__ fp16 g_qh[B_*S_*E_];
__device__ fp16 g_kh[B_*S_*E_];
__device__ fp16 g_vqh[B_*S_*VP_];
__device__ fp16 g_vkh[B_*S_*VP_];
__device__ fp16 g_fh[(size_t)B_*S_*S_];   // raw fp16 scores, then softmaxed fp16
__device__ fp16 g_q2b[B_*S_*E_];
__device__ fp16 g_k2b[B_*S_*E_];
__device__ fp16 g_q2h[B_*S_*E_];
__device__ fp16 g_k2h[B_*S_*E_];

// ---------------- PTX helpers ------------------------------------------------
__device__ __forceinline__ uint32_t smem_u32(const void* p) {
    uint32_t a;
    asm("{ .reg .u64 t; cvta.to.shared.u64 t, %1; cvt.u32.u64 %0, t; }"
        : "=r"(a) : "l"(p));
    return a;
}
__device__ __forceinline__ void cp_async16(uint32_t dst, const void* src) {
    asm volatile("cp.async.cg.shared.global [%0], [%1], 16;"
                 :: "r"(dst), "l"(src) : "memory");
}
#define CP_COMMIT() asm volatile("cp.async.commit_group;" ::: "memory")
#define CP_WAIT(n)  asm volatile("cp.async.wait_group %0;" :: "n"(n) : "memory")

#define LDMATRIX_X4(r0, r1, r2, r3, addr) \
    asm volatile("ldmatrix.sync.aligned.m8n8.x4.shared.b16 {%0,%1,%2,%3}, [%4];" \
        : "=r"(r0), "=r"(r1), "=r"(r2), "=r"(r3) : "r"(addr))

#define LDMATRIX_X4_T(r0, r1, r2, r3, addr) \
    asm volatile("ldmatrix.sync.aligned.m8n8.x4.trans.shared.b16 {%0,%1,%2,%3}, [%4];" \
        : "=r"(r0), "=r"(r1), "=r"(r2), "=r"(r3) : "r"(addr))

#define MMA_F16(d, a, b) \
    asm volatile("mma.sync.aligned.m16n8k16.row.col.f32.f16.f16.f32 " \
        "{%0,%1,%2,%3},{%4,%5,%6,%7},{%8,%9},{%0,%1,%2,%3};" \
        : "+f"((d)[0]), "+f"((d)[1]), "+f"((d)[2]), "+f"((d)[3]) \
        : "r"((a)[0]), "r"((a)[1]), "r"((a)[2]), "r"((a)[3]), \
          "r"((b)[0]), "r"((b)[1]))

// ---------------- fp16 HMMA GEMM (NT/NN, paired, fp16 beta-base) -------------
// BK=32, 5-stage cp.async ring, CP_WAIT(3) = 3 complete tiles in flight.
constexpr int HM_BM = 128, HM_BN = 128, HM_BK = 32;
constexpr int HM_LDSA = HM_BK + 8;
constexpr int HM_TILEA_B = HM_BM * HM_LDSA * 2; // 10240 bytes (also NT B tile)
constexpr int HM_LDSB = HM_BN + 8;              // NN B row stride (elems)
constexpr int HM_STAGE_B = 20480;
constexpr int HM_NSTAGE = 5;
constexpr int HM_SMEM_BYTES = HM_NSTAGE * HM_STAGE_B;   // 102400

template<bool NT, bool BM16, bool PAIR>
__global__ void __launch_bounds__(256, 2)
hmma_g(const fp16* __restrict__ A0, const fp16* __restrict__ A1,
       const fp16* __restrict__ B0, const fp16* __restrict__ B1,
       float* __restrict__ C0, float* __restrict__ C1,
       fp16* __restrict__ O0, fp16* __restrict__ O1,
       const fp16* __restrict__ P0, const fp16* __restrict__ P1,
       const float* __restrict__ bias0, const float* __restrict__ bias1,
       int M, int N, int K, int lda, int ldb, int ldc,
       long long sA, long long sB, long long sC, long long sBias,
       float alpha0, float alpha1, float beta)
{
    extern __shared__ fp16 sm[];
    const uint32_t sbase = smem_u32(sm);

    int sel, zb;
    if (PAIR) { sel = blockIdx.z & 1; zb = blockIdx.z >> 1; }
    else      { sel = 0;              zb = blockIdx.z; }

    const fp16* Ah = (PAIR && sel ? A1 : A0) + (long long)zb * sA;
    const fp16* Bh = (PAIR && sel ? B1 : B0) + (long long)zb * sB;
    float* C  = (PAIR && sel) ? C1 : C0;
    fp16*  Oh = (PAIR && sel) ? O1 : O0;
    const fp16* P = BM16 ? ((PAIR && sel) ? P1 : P0) : nullptr;
    const float* bias = (PAIR && sel) ? bias1 : bias0;
    const float alpha = (PAIR && sel) ? alpha1 : alpha0;
    const long long co = (long long)zb * sC;
    const float* bp = bias ? (bias + (long long)zb * sBias) : nullptr;

    const int tid = threadIdx.x;
    const int warp = tid >> 5, lane = tid & 31;
    const int wm = warp & 3, wn = warp >> 2;         // 4x2 warps: 32m x 64n
    const int bm = blockIdx.y * HM_BM;
    const int bn = blockIdx.x * HM_BN;
    const int NT_ = K / HM_BK;

    const int c0 = tid, c1 = tid + 256;
    const int r0c = c0 >> 2, e0c = (c0 & 3) * 8;
    const int r1c = c1 >> 2, e1c = (c1 & 3) * 8;
    const int rB0 = c0 >> 4, eB0 = (c0 & 15) * 8;
    const int rB1 = c1 >> 4, eB1 = (c1 & 15) * 8;

    auto issue = [&](int it) {
        if (it >= NT_) return;
        const uint32_t sb0 = sbase + (uint32_t)(it % HM_NSTAGE) * HM_STAGE_B;
        const long long ko = (long long)it * HM_BK;
        cp_async16(sb0 + (uint32_t)(r0c * HM_LDSA + e0c) * 2,
                   Ah + (long long)(bm + r0c) * lda + ko + e0c);
        cp_async16(sb0 + (uint32_t)(r1c * HM_LDSA + e1c) * 2,
                   Ah + (long long)(bm + r1c) * lda + ko + e1c);
        if (NT) {
            cp_async16(sb0 + HM_TILEA_B + (uint32_t)(r0c * HM_LDSA + e0c) * 2,
                       Bh + (long long)(bn + r0c) * ldb + ko + e0c);
            cp_async16(sb0 + HM_TILEA_B + (uint32_t)(r1c * HM_LDSA + e1c) * 2,
                       Bh + (long long)(bn + r1c) * ldb + ko + e1c);
        } else {
            cp_async16(sb0 + HM_TILEA_B + (uint32_t)(rB0 * HM_LDSB + eB0) * 2,
                       Bh + (ko + rB0) * (long long)ldb + bn + eB0);
            cp_async16(sb0 + HM_TILEA_B + (uint32_t)(rB1 * HM_LDSB + eB1) * 2,
                       Bh + (ko + rB1) * (long long)ldb + bn + eB1);
        }
    };

    float acc[2][8][4];
#pragma unroll
    for (int m = 0; m < 2; m++)
#pragma unroll
        for (int n = 0; n < 8; n++)
#pragma unroll
            for (int j = 0; j < 4; j++) acc[m][n][j] = 0.f;

    issue(0); CP_COMMIT();
    issue(1); CP_COMMIT();
    issue(2); CP_COMMIT();
    issue(3); CP_COMMIT();

    const int lr  = lane & 15;
    const int lc8 = (lane >> 4) << 3;

    for (int kt = 0; kt < NT_; ++kt) {
        CP_WAIT(3);                      // tile kt complete; 3 newer in flight
        __syncthreads();                 // single barrier per kt
        issue(kt + 4); CP_COMMIT();      // refills buffer (kt-1)%5, retired at barrier
        const uint32_t sb0 = sbase + (uint32_t)(kt % HM_NSTAGE) * HM_STAGE_B;
#pragma unroll
        for (int ks = 0; ks < 2; ks++) {
            const int k0 = ks * 16;
            uint32_t fA[2][4], fB[8][2];
#pragma unroll
            for (int t = 0; t < 2; t++) {
                uint32_t a = sb0 + (uint32_t)((wm*32 + t*16 + lr) * HM_LDSA + k0 + lc8) * 2;
                LDMATRIX_X4(fA[t][0], fA[t][1], fA[t][2], fA[t][3], a);
            }
            if (NT) {
#pragma unroll
                for (int p = 0; p < 4; p++) {
                    uint32_t a = sb0 + HM_TILEA_B
                               + (uint32_t)((wn*64 + p*16 + lr) * HM_LDSA + k0 + lc8) * 2;
                    uint32_t r0, r1, r2, r3;
                    LDMATRIX_X4(r0, r1, r2, r3, a);
                    fB[p*2][0]   = r0; fB[p*2][1]   = r2;
                    fB[p*2+1][0] = r1; fB[p*2+1][1] = r3;
                }
            } else {
#pragma unroll
                for (int p = 0; p < 4; p++) {
                    uint32_t a = sb0 + HM_TILEA_B
                               + (uint32_t)((k0 + lr) * HM_LDSB + wn*64 + p*16 + lc8) * 2;
                    uint32_t r0, r1, r2, r3;
                    LDMATRIX_X4_T(r0, r1, r2, r3, a);
                    fB[p*2][0]   = r0; fB[p*2][1]   = r1;
                    fB[p*2+1][0] = r2; fB[p*2+1][1] = r3;
                }
            }
#pragma unroll
            for (int m = 0; m < 2; m++)
#pragma unroll
                for (int n = 0; n < 8; n++) MMA_F16(acc[m][n], fA[m], fB[n]);
        }
    }

    // epilogue
    const int qr = lane >> 2, qc = (lane & 3) * 2;
#pragma unroll
    for (int mt = 0; mt < 2; mt++) {
#pragma unroll
        for (int nt = 0; nt < 8; nt++) {
            const int col = bn + wn*64 + nt*8 + qc;
#pragma unroll
            for (int h = 0; h < 2; h++) {
                const int row = bm + wm*32 + mt*16 + qr + h*8;
                const long long o = co + (long long)row * ldc + col;
                float2 v;
                v.x = alpha * acc[mt][nt][h*2 + 0];
                v.y = alpha * acc[mt][nt][h*2 + 1];
                if (BM16) {
                    __half2 pb = *(const __half2*)(P + o);
                    v.x += beta * __half2float(__low2half(pb));
                    v.y += beta * __half2float(__high2half(pb));
                }
                if (bp) { v.x += bp[col]; v.y += bp[col + 1]; }
                if (C)  *(float2*)(C + o) = v;
                if (Oh) *(__half2*)(Oh + o) =
                        __halves2half2(__float2half_rn(v.x), __float2half_rn(v.y));
            }
        }
    }
}

// ---------------- convert kernels --------------------------------------------
template<bool TANH>
__global__ void cvt2_k(const float* __restrict__ x0, const float* __restrict__ x1,
                       fp16* __restrict__ h0, fp16* __restrict__ h1, long long n)
{
    const float* x = blockIdx.y ? x1 : x0;
    fp16* h = blockIdx.y ? h1 : h0;
    long long i = ((long long)blockIdx.x * blockDim.x + threadIdx.x) * 4;
    if (i >= n) return;
    float4 v = *(const float4*)(x + i);
    if (TANH) { v.x = tanhf(v.x); v.y = tanhf(v.y); v.z = tanhf(v.z); v.w = tanhf(v.w); }
    __half2* hp = (__half2*)(h + i);
    hp[0] = __halves2half2(__float2half_rn(v.x), __float2half_rn(v.y));
    hp[1] = __halves2half2(__float2half_rn(v.z), __float2half_rn(v.w));
}

__global__ void cvt3_k(const float* __restrict__ x0, const float* __restrict__ x1,
                       const float* __restrict__ x2,
                       fp16* __restrict__ h0, fp16* __restrict__ h1,
                       fp16* __restrict__ h2, long long n)
{
    const float* x = (blockIdx.y == 0) ? x0 : (blockIdx.y == 1) ? x1 : x2;
    fp16* h = (blockIdx.y == 0) ? h0 : (blockIdx.y == 1) ? h1 : h2;
    long long i = ((long long)blockIdx.x * blockDim.x + threadIdx.x) * 4;
    if (i >= n) return;
    float4 v = *(const float4*)(x + i);
    __half2* hp = (__half2*)(h + i);
    hp[0] = __halves2half2(__float2half_rn(v.x), __float2half_rn(v.y));
    hp[1] = __halves2half2(__float2half_rn(v.z), __float2half_rn(v.w));
}

__global__ void padcvtW2_k(const float* __restrict__ W0, const float* __restrict__ W1,
                           fp16* __restrict__ h0, fp16* __restrict__ h1)
{
    const float* W = blockIdx.y ? W1 : W0;
    fp16* h = blockIdx.y ? h1 : h0;
    long long i = ((long long)blockIdx.x * blockDim.x + threadIdx.x) * 4;
    if (i >= 64 * E_) return;
    int r = (int)(i / E_), e = (int)(i % E_);
    float4 v = make_float4(0.f, 0.f, 0.f, 0.f);
    if (r < SV_) v = *(const float4*)(W + (long long)r * E_ + e);
    __half2* hp = (__half2*)(h + i);
    hp[0] = __halves2half2(__float2half_rn(v.x), __float2half_rn(v.y));
    hp[1] = __halves2half2(__float2half_rn(v.z), __float2half_rn(v.w));
}

__global__ void padcvtV_k(const float* __restrict__ V, fp16* __restrict__ h)
{
    long long i = ((long long)blockIdx.x * blockDim.x + threadIdx.x) * 4;
    if (i >= (long long)B_ * VP_ * E_) return;
    int b = (int)(i / (VP_ * E_));
    int rem = (int)(i % (VP_ * E_));
    int r = rem / E_, e = rem % E_;
    float4 v = make_float4(0.f, 0.f, 0.f, 0.f);
    if (r < SV_) {
        v = *(const float4*)(V + ((long long)(b * SV_ + r)) * E_ + e);
        v.x = tanhf(v.x); v.y = tanhf(v.y); v.z = tanhf(v.z); v.w = tanhf(v.w);
    }
    __half2* hp = (__half2*)(h + i);
    hp[0] = __halves2half2(__float2half_rn(v.x), __float2half_rn(v.y));
    hp[1] = __halves2half2(__float2half_rn(v.z), __float2half_rn(v.w));
}

// ---------------- softmax: fp16 scores in-place -> fp32 f + fp16 fh ----------
// cols must equal 8*256 = 2048
__global__ void softmax_cvt(fp16* __restrict__ h, float* __restrict__ x, int cols)
{
    long long r = blockIdx.x;
    fp16* hp = h + r * (long long)cols;
    float* p = x + r * (long long)cols;
    __shared__ float red[256];
    const int t = threadIdx.x;

    float vals[8];
#pragma unroll
    for (int i = 0; i < 8; i++) vals[i] = __half2float(hp[t + i * 256]);

    float mx = vals[0];
#pragma unroll
    for (int i = 1; i < 8; i++) mx = fmaxf(mx, vals[i]);
    red[t] = mx; __syncthreads();
    for (int s = 128; s > 0; s >>= 1) { if (t < s) red[t] = fmaxf(red[t], red[t + s]); __syncthreads(); }
    mx = red[0]; __syncthreads();

    float sum = 0.f;
#pragma unroll
    for (int i = 0; i < 8; i++) { vals[i] = expf(vals[i] - mx); sum += vals[i]; }
    red[t] = sum; __syncthreads();
    for (int s = 128; s > 0; s >>= 1) { if (t < s) red[t] += red[t + s]; __syncthreads(); }
    const float inv = 1.f / red[0];

#pragma unroll
    for (int i = 0; i < 8; i++) {
        float val = vals[i] * inv;
        p[t + i * 256] = val;
        hp[t + i * 256] = __float2half_rn(val);
    }
}

// ---------------- two-phase column sum (deterministic, parallel) -------------
// phase 1: grid (E/256, B, CSCH), each block sums T/CSCH rows of one chunk
__global__ void colsum_p1(const fp16* __restrict__ x, float* __restrict__ part,
                          int T, int E)
{
    int e = blockIdx.x * blockDim.x + threadIdx.x;
    int b = blockIdx.y, ch = blockIdx.z;
    const int rows = T / CSCH;
    const fp16* p = x + (long long)b * T * E + (long long)ch * rows * E + e;
    float s = 0.f;
    for (int t = 0; t < rows; t++) s += __half2float(p[(long long)t * E]);
    part[((long long)ch * B_ + b) * E_ + e] = s;
}

// phase 2: grid (E/256, B)
__global__ void colsum_p2(const float* __restrict__ part, float* __restrict__ out)
{
    int e = blockIdx.x * blockDim.x + threadIdx.x;
    int b = blockIdx.y;
    float s = 0.f;
#pragma unroll
    for (int ch = 0; ch < CSCH; ch++)
        s += part[((long long)ch * B_ + b) * E_ + e];
    out[(long long)b * E_ + e] = s;
}

// ---------------- host launcher ----------------------------------------------
extern "C" void kernel_launch(void* const* d_in, const int* in_sizes, int n_in,
                              void* d_out, int out_size)
{
    const float* Q    = (const float*)d_in[0];
    const float* K    = (const float*)d_in[1];
    const float* V    = (const float*)d_in[2];
    const float* W_Q  = (const float*)d_in[3];
    const float* W_K  = (const float*)d_in[4];
    const float* W_v  = (const float*)d_in[5];
    const float* W_vq = (const float*)d_in[6];
    const float* W_vk = (const float*)d_in[7];

    float* out  = (float*)d_out;
    float* outQ = out;
    float* outK = out + (long long)B_ * S_ * E_;
    float* f    = out + 2ll * B_ * S_ * E_;

    float *cs, *cs2, *part;
    cudaGetSymbolAddress((void**)&cs,   g_cs);
    cudaGetSymbolAddress((void**)&cs2,  g_cs2);
    cudaGetSymbolAddress((void**)&part, g_part);

    fp16 *Qs,*Ks,*Wq16,*Wk16,*Wv16,*Wvq16,*Wvk16,*Vp,*vh;
    fp16 *qh,*kh,*vqh,*vkh,*fh,*q2b,*k2b,*q2h,*k2h;
    cudaGetSymbolAddress((void**)&Qs,    g_Qs);
    cudaGetSymbolAddress((void**)&Ks,    g_Ks);
    cudaGetSymbolAddress((void**)&Wq16,  g_Wq16);
    cudaGetSymbolAddress((void**)&Wk16,  g_Wk16);
    cudaGetSymbolAddress((void**)&Wv16,  g_Wv16);
    cudaGetSymbolAddress((void**)&Wvq16, g_Wvq16);
    cudaGetSymbolAddress((void**)&Wvk16, g_Wvk16);
    cudaGetSymbolAddress((void**)&Vp,    g_Vp);
    cudaGetSymbolAddress((void**)&vh,    g_vh);
    cudaGetSymbolAddress((void**)&qh,    g_qh);
    cudaGetSymbolAddress((void**)&kh,    g_kh);
    cudaGetSymbolAddress((void**)&vqh,   g_vqh);
    cudaGetSymbolAddress((void**)&vkh,   g_vkh);
    cudaGetSymbolAddress((void**)&fh,    g_fh);
    cudaGetSymbolAddress((void**)&q2b,   g_q2b);
    cudaGetSymbolAddress((void**)&k2b,   g_k2b);
    cudaGetSymbolAddress((void**)&q2h,   g_q2h);
    cudaGetSymbolAddress((void**)&k2h,   g_k2h);

    cudaFuncSetAttribute(hmma_g<false,false,false>, cudaFuncAttributeMaxDynamicSharedMemorySize, HM_SMEM_BYTES);
    cudaFuncSetAttribute(hmma_g<false,false,true >, cudaFuncAttributeMaxDynamicSharedMemorySize, HM_SMEM_BYTES);
    cudaFuncSetAttribute(hmma_g<true ,false,false>, cudaFuncAttributeMaxDynamicSharedMemorySize, HM_SMEM_BYTES);
    cudaFuncSetAttribute(hmma_g<true ,false,true >, cudaFuncAttributeMaxDynamicSharedMemorySize, HM_SMEM_BYTES);
    cudaFuncSetAttribute(hmma_g<false,true ,true >, cudaFuncAttributeMaxDynamicSharedMemorySize, HM_SMEM_BYTES);

    const float inv = 1.0f / 32.0f;  // 1/sqrt(1024)
    const long long sQE = (long long)S_ * E_;
    const long long sSS = (long long)S_ * S_;
    const long long sVE = (long long)VP_ * E_;
    const long long sSV = (long long)S_ * VP_;
    const long long nQE = (long long)B_ * S_ * E_;

    // ---- stage 0: input conversions ----------------------------------------
    cvt2_k<true><<<dim3((int)(nQE/4/256), 2), 256>>>(Q, K, Qs, Ks, nQE);
    cvt3_k<<<dim3((int)((long long)E_*E_/4/256), 3), 256>>>(
        W_Q, W_K, W_v, Wq16, Wk16, Wv16, (long long)E_*E_);
    padcvtW2_k<<<dim3(64, 2), 256>>>(W_vq, W_vk, Wvq16, Wvk16);
    padcvtV_k<<<(int)((long long)B_*VP_*E_/4/256), 256>>>(V, Vp);

    // ---- stage 1: paired Q/K projections (NN, fp16 out only) + v -----------
    hmma_g<false,false,true><<<dim3(8,64,2), 256, HM_SMEM_BYTES>>>(
        Qs, Ks, Wq16, Wk16, nullptr, nullptr, qh, kh, nullptr, nullptr,
        nullptr, nullptr,
        B_*S_, E_, E_, E_, E_, E_, 0,0,0,0, 1.f, 1.f, 0.f);
    hmma_g<false,false,false><<<dim3(8,(B_*VP_)/128,1), 256, HM_SMEM_BYTES>>>(
        Vp, nullptr, Wv16, nullptr, nullptr, nullptr, vh, nullptr, nullptr, nullptr,
        nullptr, nullptr,
        B_*VP_, E_, E_, E_, E_, E_, 0,0,0,0, 1.f, 0.f, 0.f);

    colsum_p1<<<dim3(E_/256, B_, CSCH), 256>>>(kh, part, S_, E_);
    colsum_p2<<<dim3(E_/256, B_), 256>>>(part, cs);

    // ---- stage 3: raw fp16 scores -> softmax (writes fp32 f + fp16 fh) -----
    hmma_g<true,false,false><<<dim3(16,16,B_), 256, HM_SMEM_BYTES>>>(
        qh, nullptr, kh, nullptr, nullptr, nullptr, fh, nullptr, nullptr, nullptr,
        nullptr, nullptr,
        S_, S_, E_, E_, E_, S_, sQE, sQE, sSS, 0, inv, 0.f, 0.f);
    softmax_cvt<<<B_*S_, 256>>>(fh, f, S_);

    // ---- vq/vk paired (NT, N=VP=128) + q2/k2 base paired (NN) --------------
    hmma_g<true,false,true><<<dim3(VP_/128,16,2*B_), 256, HM_SMEM_BYTES>>>(
        qh, kh, vh, vh, nullptr, nullptr, vqh, vkh, nullptr, nullptr,
        nullptr, nullptr,
        S_, VP_, E_, E_, E_, VP_, sQE, sVE, sSV, 0, inv, inv, 0.f);
    hmma_g<false,false,true><<<dim3(8,16,2*B_), 256, HM_SMEM_BYTES>>>(
        vqh, vkh, Wvq16, Wvk16, nullptr, nullptr, q2b, k2b, nullptr, nullptr,
        nullptr, cs,
        S_, E_, 64, VP_, E_, E_, sSV, 0, sQE, E_, 1.f, 1.f, 0.f);

    // ---- stage 4: q2 = f@q + q2b ; k2 = -(f@k) + k2b (fp16 base + out) -----
    hmma_g<false,true,true><<<dim3(8,16,2*B_), 256, HM_SMEM_BYTES>>>(
        fh, fh, qh, kh, nullptr, nullptr, q2h, k2h, q2b, k2b,
        nullptr, nullptr,
        S_, E_, S_, S_, E_, E_, sSS, sQE, sQE, 0, 1.f, -1.f, 1.f);

    colsum_p1<<<dim3(E_/256, B_, CSCH), 256>>>(k2h, part, S_, E_);
    colsum_p2<<<dim3(E_/256, B_), 256>>>(part, cs2);

    // ---- stage 5: outputs (paired NN) --------------------------------------
    hmma_g<false,false,true><<<dim3(8,16,2*B_), 256, HM_SMEM_BYTES>>>(
        fh, fh, q2h, k2h, outQ, outK, nullptr, nullptr, nullptr, nullptr,
        nullptr, cs2,
        S_, E_, S_, S_, E_, E_, sSS, sQE, sQE, E_, 1.f, -1.f, 0.f);

    (void)in_sizes; (void)n_in; (void)out_size;
}

// round 17
// speedup vs baseline: 1.7986x; 1.0359x over previous
#include <cuda_runtime.h>
#include <cuda_fp16.h>
#include <math.h>
#include <stdint.h>

#define B_  4
#define S_  2048
#define SV_ 50
#define E_  1024
#define VP_ 128   // padded v rows per batch
#define CSCH 32   // colsum chunks

typedef __half fp16;

// ---------------- scratch (device globals) ----------------------------------
__device__ float g_cs [B_*E_];
__device__ float g_cs2[B_*E_];
__device__ float g_part[CSCH*B_*E_];

__device__ fp16 g_Qs[B_*S_*E_];
__device__ fp16 g_Ks[B_*S_*E_];
__device__ fp16 g_Wq16[E_*E_];
__device__ fp16 g_Wk16[E_*E_];
__device__ fp16 g_Wv16[E_*E_];
__device__ fp16 g_Wvq16[64*E_];
__device__ fp16 g_Wvk16[64*E_];
__device__ fp16 g_Vp[B_*VP_*E_];
__device__ fp16 g_vh[B_*VP_*E_];
__device__ fp16 g_qh[B_*S_*E_];
__device__ fp16 g_kh[B_*S_*E_];
__device__ fp16 g_vqh[B_*S_*VP_];
__device__ fp16 g_vkh[B_*S_*VP_];
__device__ fp16 g_fh[(size_t)B_*S_*S_];   // raw fp16 scores, then softmaxed fp16
__device__ fp16 g_q2b[B_*S_*E_];
__device__ fp16 g_k2b[B_*S_*E_];
__device__ fp16 g_q2h[B_*S_*E_];
__device__ fp16 g_k2h[B_*S_*E_];

// ---------------- PTX helpers ------------------------------------------------
__device__ __forceinline__ uint32_t smem_u32(const void* p) {
    uint32_t a;
    asm("{ .reg .u64 t; cvta.to.shared.u64 t, %1; cvt.u32.u64 %0, t; }"
        : "=r"(a) : "l"(p));
    return a;
}
__device__ __forceinline__ void cp_async16(uint32_t dst, const void* src) {
    asm volatile("cp.async.cg.shared.global [%0], [%1], 16;"
                 :: "r"(dst), "l"(src) : "memory");
}
#define CP_COMMIT() asm volatile("cp.async.commit_group;" ::: "memory")
#define CP_WAIT(n)  asm volatile("cp.async.wait_group %0;" :: "n"(n) : "memory")

#define LDMATRIX_X4(r0, r1, r2, r3, addr) \
    asm volatile("ldmatrix.sync.aligned.m8n8.x4.shared.b16 {%0,%1,%2,%3}, [%4];" \
        : "=r"(r0), "=r"(r1), "=r"(r2), "=r"(r3) : "r"(addr))

#define LDMATRIX_X4_T(r0, r1, r2, r3, addr) \
    asm volatile("ldmatrix.sync.aligned.m8n8.x4.trans.shared.b16 {%0,%1,%2,%3}, [%4];" \
        : "=r"(r0), "=r"(r1), "=r"(r2), "=r"(r3) : "r"(addr))

#define MMA_F16(d, a, b) \
    asm volatile("mma.sync.aligned.m16n8k16.row.col.f32.f16.f16.f32 " \
        "{%0,%1,%2,%3},{%4,%5,%6,%7},{%8,%9},{%0,%1,%2,%3};" \
        : "+f"((d)[0]), "+f"((d)[1]), "+f"((d)[2]), "+f"((d)[3]) \
        : "r"((a)[0]), "r"((a)[1]), "r"((a)[2]), "r"((a)[3]), \
          "r"((b)[0]), "r"((b)[1]))

// ---------------- fp16 HMMA GEMM core (NT/NN) --------------------------------
// BK=32, 5-stage cp.async ring, CP_WAIT(3) = 3 complete tiles in flight.
constexpr int HM_BM = 128, HM_BN = 128, HM_BK = 32;
constexpr int HM_LDSA = HM_BK + 8;
constexpr int HM_TILEA_B = HM_BM * HM_LDSA * 2; // 10240 bytes (also NT B tile)
constexpr int HM_LDSB = HM_BN + 8;              // NN B row stride (elems)
constexpr int HM_STAGE_B = 20480;
constexpr int HM_NSTAGE = 5;
constexpr int HM_SMEM_BYTES = HM_NSTAGE * HM_STAGE_B;   // 102400

template<bool NT, bool BM16>
__device__ __forceinline__ void gemm_core(
    const fp16* __restrict__ Ah, const fp16* __restrict__ Bh,
    float* __restrict__ C, fp16* __restrict__ Oh,
    const fp16* __restrict__ P, const float* __restrict__ bp,
    int bm, int bn, int K, int lda, int ldb, int ldc, long long co,
    float alpha, float beta, fp16* sm)
{
    const uint32_t sbase = smem_u32(sm);
    const int tid = threadIdx.x;
    const int warp = tid >> 5, lane = tid & 31;
    const int wm = warp & 3, wn = warp >> 2;         // 4x2 warps: 32m x 64n
    const int NT_ = K / HM_BK;

    const int c0 = tid, c1 = tid + 256;
    const int r0c = c0 >> 2, e0c = (c0 & 3) * 8;
    const int r1c = c1 >> 2, e1c = (c1 & 3) * 8;
    const int rB0 = c0 >> 4, eB0 = (c0 & 15) * 8;
    const int rB1 = c1 >> 4, eB1 = (c1 & 15) * 8;

    auto issue = [&](int it) {
        if (it >= NT_) return;
        const uint32_t sb0 = sbase + (uint32_t)(it % HM_NSTAGE) * HM_STAGE_B;
        const long long ko = (long long)it * HM_BK;
        cp_async16(sb0 + (uint32_t)(r0c * HM_LDSA + e0c) * 2,
                   Ah + (long long)(bm + r0c) * lda + ko + e0c);
        cp_async16(sb0 + (uint32_t)(r1c * HM_LDSA + e1c) * 2,
                   Ah + (long long)(bm + r1c) * lda + ko + e1c);
        if (NT) {
            cp_async16(sb0 + HM_TILEA_B + (uint32_t)(r0c * HM_LDSA + e0c) * 2,
                       Bh + (long long)(bn + r0c) * ldb + ko + e0c);
            cp_async16(sb0 + HM_TILEA_B + (uint32_t)(r1c * HM_LDSA + e1c) * 2,
                       Bh + (long long)(bn + r1c) * ldb + ko + e1c);
        } else {
            cp_async16(sb0 + HM_TILEA_B + (uint32_t)(rB0 * HM_LDSB + eB0) * 2,
                       Bh + (ko + rB0) * (long long)ldb + bn + eB0);
            cp_async16(sb0 + HM_TILEA_B + (uint32_t)(rB1 * HM_LDSB + eB1) * 2,
                       Bh + (ko + rB1) * (long long)ldb + bn + eB1);
        }
    };

    float acc[2][8][4];
#pragma unroll
    for (int m = 0; m < 2; m++)
#pragma unroll
        for (int n = 0; n < 8; n++)
#pragma unroll
            for (int j = 0; j < 4; j++) acc[m][n][j] = 0.f;

    issue(0); CP_COMMIT();
    issue(1); CP_COMMIT();
    issue(2); CP_COMMIT();
    issue(3); CP_COMMIT();

    const int lr  = lane & 15;
    const int lc8 = (lane >> 4) << 3;

    for (int kt = 0; kt < NT_; ++kt) {
        CP_WAIT(3);                      // tile kt complete; 3 newer in flight
        __syncthreads();                 // single barrier per kt
        issue(kt + 4); CP_COMMIT();      // refills retired buffer (kt-1)%5
        const uint32_t sb0 = sbase + (uint32_t)(kt % HM_NSTAGE) * HM_STAGE_B;
#pragma unroll
        for (int ks = 0; ks < 2; ks++) {
            const int k0 = ks * 16;
            uint32_t fA[2][4], fB[8][2];
#pragma unroll
            for (int t = 0; t < 2; t++) {
                uint32_t a = sb0 + (uint32_t)((wm*32 + t*16 + lr) * HM_LDSA + k0 + lc8) * 2;
                LDMATRIX_X4(fA[t][0], fA[t][1], fA[t][2], fA[t][3], a);
            }
            if (NT) {
#pragma unroll
                for (int p = 0; p < 4; p++) {
                    uint32_t a = sb0 + HM_TILEA_B
                               + (uint32_t)((wn*64 + p*16 + lr) * HM_LDSA + k0 + lc8) * 2;
                    uint32_t r0, r1, r2, r3;
                    LDMATRIX_X4(r0, r1, r2, r3, a);
                    fB[p*2][0]   = r0; fB[p*2][1]   = r2;
                    fB[p*2+1][0] = r1; fB[p*2+1][1] = r3;
                }
            } else {
#pragma unroll
                for (int p = 0; p < 4; p++) {
                    uint32_t a = sb0 + HM_TILEA_B
                               + (uint32_t)((k0 + lr) * HM_LDSB + wn*64 + p*16 + lc8) * 2;
                    uint32_t r0, r1, r2, r3;
                    LDMATRIX_X4_T(r0, r1, r2, r3, a);
                    fB[p*2][0]   = r0; fB[p*2][1]   = r1;
                    fB[p*2+1][0] = r2; fB[p*2+1][1] = r3;
                }
            }
#pragma unroll
            for (int m = 0; m < 2; m++)
#pragma unroll
                for (int n = 0; n < 8; n++) MMA_F16(acc[m][n], fA[m], fB[n]);
        }
    }

    // epilogue
    const int qr = lane >> 2, qc = (lane & 3) * 2;
#pragma unroll
    for (int mt = 0; mt < 2; mt++) {
#pragma unroll
        for (int nt = 0; nt < 8; nt++) {
            const int col = bn + wn*64 + nt*8 + qc;
#pragma unroll
            for (int h = 0; h < 2; h++) {
                const int row = bm + wm*32 + mt*16 + qr + h*8;
                const long long o = co + (long long)row * ldc + col;
                float2 v;
                v.x = alpha * acc[mt][nt][h*2 + 0];
                v.y = alpha * acc[mt][nt][h*2 + 1];
                if (BM16) {
                    __half2 pb = *(const __half2*)(P + o);
                    v.x += beta * __half2float(__low2half(pb));
                    v.y += beta * __half2float(__high2half(pb));
                }
                if (bp) { v.x += bp[col]; v.y += bp[col + 1]; }
                if (C)  *(float2*)(C + o) = v;
                if (Oh) *(__half2*)(Oh + o) =
                        __halves2half2(__float2half_rn(v.x), __float2half_rn(v.y));
            }
        }
    }
}

// ---------------- generic paired wrapper (base / stage4 / stage5) ------------
template<bool NT, bool BM16, bool PAIR>
__global__ void __launch_bounds__(256, 2)
hmma_g(const fp16* __restrict__ A0, const fp16* __restrict__ A1,
       const fp16* __restrict__ B0, const fp16* __restrict__ B1,
       float* __restrict__ C0, float* __restrict__ C1,
       fp16* __restrict__ O0, fp16* __restrict__ O1,
       const fp16* __restrict__ P0, const fp16* __restrict__ P1,
       const float* __restrict__ bias0, const float* __restrict__ bias1,
       int M, int N, int K, int lda, int ldb, int ldc,
       long long sA, long long sB, long long sC, long long sBias,
       float alpha0, float alpha1, float beta)
{
    extern __shared__ fp16 sm[];
    int sel, zb;
    if (PAIR) { sel = blockIdx.z & 1; zb = blockIdx.z >> 1; }
    else      { sel = 0;              zb = blockIdx.z; }

    const fp16* Ah = (PAIR && sel ? A1 : A0) + (long long)zb * sA;
    const fp16* Bh = (PAIR && sel ? B1 : B0) + (long long)zb * sB;
    float* C  = (PAIR && sel) ? C1 : C0;
    fp16*  Oh = (PAIR && sel) ? O1 : O0;
    const fp16* P = BM16 ? ((PAIR && sel) ? P1 : P0) : nullptr;
    const float* bias = (PAIR && sel) ? bias1 : bias0;
    const float alpha = (PAIR && sel) ? alpha1 : alpha0;
    const long long co = (long long)zb * sC;
    const float* bp = bias ? (bias + (long long)zb * sBias) : nullptr;

    gemm_core<NT, BM16>(Ah, Bh, C, Oh, P, bp,
                        blockIdx.y * HM_BM, blockIdx.x * HM_BN,
                        K, lda, ldb, ldc, co, alpha, beta, sm);
}

// ---------------- fused Q/K/v projection (NN) --------------------------------
// grid (8, 66, 2): y<64 -> Q/K proj (sel by z); y>=64 -> v proj (4 M-tiles
// split across (y-64, z)).
__global__ void __launch_bounds__(256, 2)
proj_fused(const fp16* __restrict__ Qs, const fp16* __restrict__ Ks,
           const fp16* __restrict__ Wq, const fp16* __restrict__ Wk,
           fp16* __restrict__ qh, fp16* __restrict__ kh,
           const fp16* __restrict__ Vp, const fp16* __restrict__ Wv,
           fp16* __restrict__ vh)
{
    extern __shared__ fp16 sm[];
    const int sel = blockIdx.z;
    const fp16 *A, *Bm; fp16* O; int bm;
    if (blockIdx.y < 64) {
        A = sel ? Ks : Qs;  Bm = sel ? Wk : Wq;  O = sel ? kh : qh;
        bm = blockIdx.y * HM_BM;
    } else {
        A = Vp;  Bm = Wv;  O = vh;
        bm = ((int)(blockIdx.y - 64) * 2 + sel) * HM_BM;   // 0..3 tiles of M=512
    }
    gemm_core<false, false>(A, Bm, nullptr, O, nullptr, nullptr,
                            bm, blockIdx.x * HM_BN,
                            E_, E_, E_, E_, 0, 1.f, 0.f, sm);
}

// ---------------- fused qk^T + vq + vk (NT) ----------------------------------
// grid (18, 16, 4): x<16 -> scores fh; x==16 -> vq; x==17 -> vk.
__global__ void __launch_bounds__(256, 2)
qkvv_fused(const fp16* __restrict__ qh, const fp16* __restrict__ kh,
           const fp16* __restrict__ vh,
           fp16* __restrict__ fh, fp16* __restrict__ vqh, fp16* __restrict__ vkh)
{
    extern __shared__ fp16 sm[];
    const int b = blockIdx.z;
    const float inv = 1.0f / 32.0f;
    const long long sQE = (long long)S_ * E_;
    const fp16 *A, *Bm; fp16* O; int bn, ldc; long long co;
    if (blockIdx.x < 16) {
        A = qh + (long long)b * sQE;  Bm = kh + (long long)b * sQE;
        O = fh;  bn = blockIdx.x * HM_BN;  ldc = S_;
        co = (long long)b * S_ * S_;
    } else {
        A = (blockIdx.x == 16 ? qh : kh) + (long long)b * sQE;
        Bm = vh + (long long)b * VP_ * E_;
        O = (blockIdx.x == 16) ? vqh : vkh;
        bn = 0;  ldc = VP_;
        co = (long long)b * S_ * VP_;
    }
    gemm_core<true, false>(A, Bm, nullptr, O, nullptr, nullptr,
                           blockIdx.y * HM_BM, bn,
                           E_, E_, E_, ldc, co, inv, 0.f, sm);
}

// ---------------- convert kernels --------------------------------------------
template<bool TANH>
__global__ void cvt2_k(const float* __restrict__ x0, const float* __restrict__ x1,
                       fp16* __restrict__ h0, fp16* __restrict__ h1, long long n)
{
    const float* x = blockIdx.y ? x1 : x0;
    fp16* h = blockIdx.y ? h1 : h0;
    long long i = ((long long)blockIdx.x * blockDim.x + threadIdx.x) * 4;
    if (i >= n) return;
    float4 v = *(const float4*)(x + i);
    if (TANH) { v.x = tanhf(v.x); v.y = tanhf(v.y); v.z = tanhf(v.z); v.w = tanhf(v.w); }
    __half2* hp = (__half2*)(h + i);
    hp[0] = __halves2half2(__float2half_rn(v.x), __float2half_rn(v.y));
    hp[1] = __halves2half2(__float2half_rn(v.z), __float2half_rn(v.w));
}

__global__ void cvt3_k(const float* __restrict__ x0, const float* __restrict__ x1,
                       const float* __restrict__ x2,
                       fp16* __restrict__ h0, fp16* __restrict__ h1,
                       fp16* __restrict__ h2, long long n)
{
    const float* x = (blockIdx.y == 0) ? x0 : (blockIdx.y == 1) ? x1 : x2;
    fp16* h = (blockIdx.y == 0) ? h0 : (blockIdx.y == 1) ? h1 : h2;
    long long i = ((long long)blockIdx.x * blockDim.x + threadIdx.x) * 4;
    if (i >= n) return;
    float4 v = *(const float4*)(x + i);
    __half2* hp = (__half2*)(h + i);
    hp[0] = __halves2half2(__float2half_rn(v.x), __float2half_rn(v.y));
    hp[1] = __halves2half2(__float2half_rn(v.z), __float2half_rn(v.w));
}

__global__ void padcvtW2_k(const float* __restrict__ W0, const float* __restrict__ W1,
                           fp16* __restrict__ h0, fp16* __restrict__ h1)
{
    const float* W = blockIdx.y ? W1 : W0;
    fp16* h = blockIdx.y ? h1 : h0;
    long long i = ((long long)blockIdx.x * blockDim.x + threadIdx.x) * 4;
    if (i >= 64 * E_) return;
    int r = (int)(i / E_), e = (int)(i % E_);
    float4 v = make_float4(0.f, 0.f, 0.f, 0.f);
    if (r < SV_) v = *(const float4*)(W + (long long)r * E_ + e);
    __half2* hp = (__half2*)(h + i);
    hp[0] = __halves2half2(__float2half_rn(v.x), __float2half_rn(v.y));
    hp[1] = __halves2half2(__float2half_rn(v.z), __float2half_rn(v.w));
}

__global__ void padcvtV_k(const float* __restrict__ V, fp16* __restrict__ h)
{
    long long i = ((long long)blockIdx.x * blockDim.x + threadIdx.x) * 4;
    if (i >= (long long)B_ * VP_ * E_) return;
    int b = (int)(i / (VP_ * E_));
    int rem = (int)(i % (VP_ * E_));
    int r = rem / E_, e = rem % E_;
    float4 v = make_float4(0.f, 0.f, 0.f, 0.f);
    if (r < SV_) {
        v = *(const float4*)(V + ((long long)(b * SV_ + r)) * E_ + e);
        v.x = tanhf(v.x); v.y = tanhf(v.y); v.z = tanhf(v.z); v.w = tanhf(v.w);
    }
    __half2* hp = (__half2*)(h + i);
    hp[0] = __halves2half2(__float2half_rn(v.x), __float2half_rn(v.y));
    hp[1] = __halves2half2(__float2half_rn(v.z), __float2half_rn(v.w));
}

// ---------------- softmax: fp16 scores in-place -> fp32 f + fp16 fh ----------
// cols must equal 8*256 = 2048
__global__ void softmax_cvt(fp16* __restrict__ h, float* __restrict__ x, int cols)
{
    long long r = blockIdx.x;
    fp16* hp = h + r * (long long)cols;
    float* p = x + r * (long long)cols;
    __shared__ float red[256];
    const int t = threadIdx.x;

    float vals[8];
#pragma unroll
    for (int i = 0; i < 8; i++) vals[i] = __half2float(hp[t + i * 256]);

    float mx = vals[0];
#pragma unroll
    for (int i = 1; i < 8; i++) mx = fmaxf(mx, vals[i]);
    red[t] = mx; __syncthreads();
    for (int s = 128; s > 0; s >>= 1) { if (t < s) red[t] = fmaxf(red[t], red[t + s]); __syncthreads(); }
    mx = red[0]; __syncthreads();

    float sum = 0.f;
#pragma unroll
    for (int i = 0; i < 8; i++) { vals[i] = expf(vals[i] - mx); sum += vals[i]; }
    red[t] = sum; __syncthreads();
    for (int s = 128; s > 0; s >>= 1) { if (t < s) red[t] += red[t + s]; __syncthreads(); }
    const float inv = 1.f / red[0];

#pragma unroll
    for (int i = 0; i < 8; i++) {
        float val = vals[i] * inv;
        p[t + i * 256] = val;
        hp[t + i * 256] = __float2half_rn(val);
    }
}

// ---------------- two-phase column sum (deterministic, parallel) -------------
__global__ void colsum_p1(const fp16* __restrict__ x, float* __restrict__ part,
                          int T, int E)
{
    int e = blockIdx.x * blockDim.x + threadIdx.x;
    int b = blockIdx.y, ch = blockIdx.z;
    const int rows = T / CSCH;
    const fp16* p = x + (long long)b * T * E + (long long)ch * rows * E + e;
    float s = 0.f;
    for (int t = 0; t < rows; t++) s += __half2float(p[(long long)t * E]);
    part[((long long)ch * B_ + b) * E_ + e] = s;
}

__global__ void colsum_p2(const float* __restrict__ part, float* __restrict__ out)
{
    int e = blockIdx.x * blockDim.x + threadIdx.x;
    int b = blockIdx.y;
    float s = 0.f;
#pragma unroll
    for (int ch = 0; ch < CSCH; ch++)
        s += part[((long long)ch * B_ + b) * E_ + e];
    out[(long long)b * E_ + e] = s;
}

// ---------------- host launcher ----------------------------------------------
extern "C" void kernel_launch(void* const* d_in, const int* in_sizes, int n_in,
                              void* d_out, int out_size)
{
    const float* Q    = (const float*)d_in[0];
    const float* K    = (const float*)d_in[1];
    const float* V    = (const float*)d_in[2];
    const float* W_Q  = (const float*)d_in[3];
    const float* W_K  = (const float*)d_in[4];
    const float* W_v  = (const float*)d_in[5];
    const float* W_vq = (const float*)d_in[6];
    const float* W_vk = (const float*)d_in[7];

    float* out  = (float*)d_out;
    float* outQ = out;
    float* outK = out + (long long)B_ * S_ * E_;
    float* f    = out + 2ll * B_ * S_ * E_;

    float *cs, *cs2, *part;
    cudaGetSymbolAddress((void**)&cs,   g_cs);
    cudaGetSymbolAddress((void**)&cs2,  g_cs2);
    cudaGetSymbolAddress((void**)&part, g_part);

    fp16 *Qs,*Ks,*Wq16,*Wk16,*Wv16,*Wvq16,*Wvk16,*Vp,*vh;
    fp16 *qh,*kh,*vqh,*vkh,*fh,*q2b,*k2b,*q2h,*k2h;
    cudaGetSymbolAddress((void**)&Qs,    g_Qs);
    cudaGetSymbolAddress((void**)&Ks,    g_Ks);
    cudaGetSymbolAddress((void**)&Wq16,  g_Wq16);
    cudaGetSymbolAddress((void**)&Wk16,  g_Wk16);
    cudaGetSymbolAddress((void**)&Wv16,  g_Wv16);
    cudaGetSymbolAddress((void**)&Wvq16, g_Wvq16);
    cudaGetSymbolAddress((void**)&Wvk16, g_Wvk16);
    cudaGetSymbolAddress((void**)&Vp,    g_Vp);
    cudaGetSymbolAddress((void**)&vh,    g_vh);
    cudaGetSymbolAddress((void**)&qh,    g_qh);
    cudaGetSymbolAddress((void**)&kh,    g_kh);
    cudaGetSymbolAddress((void**)&vqh,   g_vqh);
    cudaGetSymbolAddress((void**)&vkh,   g_vkh);
    cudaGetSymbolAddress((void**)&fh,    g_fh);
    cudaGetSymbolAddress((void**)&q2b,   g_q2b);
    cudaGetSymbolAddress((void**)&k2b,   g_k2b);
    cudaGetSymbolAddress((void**)&q2h,   g_q2h);
    cudaGetSymbolAddress((void**)&k2h,   g_k2h);

    cudaFuncSetAttribute(hmma_g<false,false,true >, cudaFuncAttributeMaxDynamicSharedMemorySize, HM_SMEM_BYTES);
    cudaFuncSetAttribute(hmma_g<false,true ,true >, cudaFuncAttributeMaxDynamicSharedMemorySize, HM_SMEM_BYTES);
    cudaFuncSetAttribute(proj_fused, cudaFuncAttributeMaxDynamicSharedMemorySize, HM_SMEM_BYTES);
    cudaFuncSetAttribute(qkvv_fused, cudaFuncAttributeMaxDynamicSharedMemorySize, HM_SMEM_BYTES);

    const long long sQE = (long long)S_ * E_;
    const long long sSS = (long long)S_ * S_;
    const long long sSV = (long long)S_ * VP_;
    const long long nQE = (long long)B_ * S_ * E_;

    // ---- stage 0: input conversions ----------------------------------------
    cvt2_k<true><<<dim3((int)(nQE/4/256), 2), 256>>>(Q, K, Qs, Ks, nQE);
    cvt3_k<<<dim3((int)((long long)E_*E_/4/256), 3), 256>>>(
        W_Q, W_K, W_v, Wq16, Wk16, Wv16, (long long)E_*E_);
    padcvtW2_k<<<dim3(64, 2), 256>>>(W_vq, W_vk, Wvq16, Wvk16);
    padcvtV_k<<<(int)((long long)B_*VP_*E_/4/256), 256>>>(V, Vp);

    // ---- stage 1: fused Q/K/v projections (NN) -----------------------------
    proj_fused<<<dim3(8, 66, 2), 256, HM_SMEM_BYTES>>>(
        Qs, Ks, Wq16, Wk16, qh, kh, Vp, Wv16, vh);

    colsum_p1<<<dim3(E_/256, B_, CSCH), 256>>>(kh, part, S_, E_);
    colsum_p2<<<dim3(E_/256, B_), 256>>>(part, cs);

    // ---- stage 3: fused qk^T + vq + vk (NT) -> softmax ---------------------
    qkvv_fused<<<dim3(18, 16, B_), 256, HM_SMEM_BYTES>>>(
        qh, kh, vh, fh, vqh, vkh);
    softmax_cvt<<<B_*S_, 256>>>(fh, f, S_);

    // ---- q2/k2 base paired (NN, K=64: vq/vk cols 64.. are exact zeros) -----
    hmma_g<false,false,true><<<dim3(8,16,2*B_), 256, HM_SMEM_BYTES>>>(
        vqh, vkh, Wvq16, Wvk16, nullptr, nullptr, q2b, k2b, nullptr, nullptr,
        nullptr, cs,
        S_, E_, 64, VP_, E_, E_, sSV, 0, sQE, E_, 1.f, 1.f, 0.f);

    // ---- stage 4: q2 = f@q + q2b ; k2 = -(f@k) + k2b (fp16 base + out) -----
    hmma_g<false,true,true><<<dim3(8,16,2*B_), 256, HM_SMEM_BYTES>>>(
        fh, fh, qh, kh, nullptr, nullptr, q2h, k2h, q2b, k2b,
        nullptr, nullptr,
        S_, E_, S_, S_, E_, E_, sSS, sQE, sQE, 0, 1.f, -1.f, 1.f);

    colsum_p1<<<dim3(E_/256, B_, CSCH), 256>>>(k2h, part, S_, E_);
    colsum_p2<<<dim3(E_/256, B_), 256>>>(part, cs2);

    // ---- stage 5: outputs (paired NN) --------------------------------------
    hmma_g<false,false,true><<<dim3(8,16,2*B_), 256, HM_SMEM_BYTES>>>(
        fh, fh, q2h, k2h, outQ, outK, nullptr, nullptr, nullptr, nullptr,
        nullptr, cs2,
        S_, E_, S_, S_, E_, E_, sSS, sQE, sQE, E_, 1.f, -1.f, 0.f);

    (void)in_sizes; (void)n_in; (void)out_size;
}